// round 7
// baseline (speedup 1.0000x reference)
#include <cuda_runtime.h>
#include <math.h>
#include <stdint.h>

#define Bc 8
#define Nc 1024
#define Mc 2048
#define Dc 1024

// Scratch (allocation-free rule). All stored k-pair-PERMUTED within 8-groups:
// group g, logical offset o (0..7) lives at position 2*(o&3)+(o>>2).
__device__ float g_audioR[(size_t)Bc * Mc * Dc];   // [b][m][d_perm], tf32
__device__ float g_textR [(size_t)Bc * Nc * Dc];   // [b][n][d_perm], tf32
__device__ float g_attnP [(size_t)Bc * Nc * Mc];   // [b][n][m_perm], tf32

__device__ __forceinline__ float tf32r(float x) {
    uint32_t u;
    asm("cvt.rna.tf32.f32 %0, %1;" : "=r"(u) : "f"(x));
    return __uint_as_float(u);
}
__device__ __forceinline__ void cp_async16(uint32_t dst, const void* src) {
    asm volatile("cp.async.cg.shared.global [%0], [%1], 16;" :: "r"(dst), "l"(src) : "memory");
}
__device__ __forceinline__ void mma_tf32(float* c, const uint32_t* a, const uint32_t* b) {
    asm volatile(
        "mma.sync.aligned.m16n8k8.row.col.f32.tf32.tf32.f32 "
        "{%0,%1,%2,%3}, {%4,%5,%6,%7}, {%8,%9}, {%0,%1,%2,%3};"
        : "+f"(c[0]), "+f"(c[1]), "+f"(c[2]), "+f"(c[3])
        : "r"(a[0]), "r"(a[1]), "r"(a[2]), "r"(a[3]), "r"(b[0]), "r"(b[1]));
}

#define BM 128
#define BN 128
#define BK 32

// A tile (and gemm1 B tile): 128 rows x 16 float2 pairs, XOR-swizzled.
// f2 index = row*16 + (P ^ ((row&3)<<2)),  P = 4*ks + tg  -> (kc, kc+4) pair.
#define TILE_F2   2048          // 128*16 f2 = 16 KB
#define TILE_B    16384
// gemm2 B tile (BROW): 32 k-rows x 136 floats (pad), natural order
#define BNP       136
#define BROW_B    (32 * BNP * 4)   // 17408 B

// ---------------------------------------------------------------------------
// tf32 tensor-core GEMM, 128x128 CTA tile, 8 warps (warp tile 32x64),
// 3-stage cp.async pipeline, one __syncthreads per K-stage.
//   BROW=false: B K-major pair-permuted (gemm1); BROW=true: B [k][col] natural
//   (gemm2; cols are permuted d -> epilogue un-permutes).
// ---------------------------------------------------------------------------
template<int KTOT, bool BIAS, bool BROW>
__global__ __launch_bounds__(256, 2) void tc_gemm(
    const float* __restrict__ Ag, const float* __restrict__ Bg,
    float* __restrict__ Og,
    size_t sA, size_t sB, size_t sO,
    int ldA, int ldB, int ldO,
    const float* __restrict__ sigma)
{
    constexpr uint32_t B_BYTES = BROW ? BROW_B : TILE_B;
    constexpr uint32_t STAGE_B = TILE_B + B_BYTES;

    extern __shared__ float sm[];
    const uint32_t smemU = (uint32_t)__cvta_generic_to_shared(sm);
    const int tid  = threadIdx.x;
    const int lane = tid & 31;
    const int wid  = tid >> 5;
    const int wm0  = (wid & 3) * 32;
    const int wn0  = (wid >> 2) * 64;
    const int gq   = lane >> 2;
    const int tg   = lane & 3;

    const int b  = blockIdx.z;
    const int r0 = blockIdx.y * BM;
    const int c0 = blockIdx.x * BN;

    const float* Ab = Ag + (size_t)b * sA + (size_t)r0 * ldA;
    const float* Bb = Bg + (size_t)b * sB + (BROW ? (size_t)c0 : (size_t)c0 * ldB);

    float acc[2][8][4];
    #pragma unroll
    for (int mt = 0; mt < 2; ++mt)
        #pragma unroll
        for (int nt = 0; nt < 8; ++nt)
            #pragma unroll
            for (int r = 0; r < 4; ++r) acc[mt][nt][r] = 0.0f;

    auto issue = [&](int c) {
        const int s  = c % 3;
        const int k0 = c * BK;
        #pragma unroll
        for (int i = 0; i < 8; ++i) {
            const int q   = tid + i * 256;        // 0..2047
            const int isB = q >> 10;
            const int qq  = q & 1023;
            const float* src;
            uint32_t off;
            if (!isB) {
                const int row = qq >> 3, j = qq & 7;
                src = Ab + (size_t)row * ldA + k0 + j * 4;
                off = (uint32_t)(row * 128 + (((2 * j) ^ ((row & 3) << 2)) << 3));
            } else if (!BROW) {
                const int row = qq >> 3, j = qq & 7;
                src = Bb + (size_t)row * ldB + k0 + j * 4;
                off = TILE_B + (uint32_t)(row * 128 + (((2 * j) ^ ((row & 3) << 2)) << 3));
            } else {
                const int kr = qq >> 5, jc = qq & 31;
                src = Bb + (size_t)(k0 + kr) * ldB + jc * 4;
                off = TILE_B + (uint32_t)(kr * (BNP * 4) + jc * 16);
            }
            cp_async16(smemU + s * STAGE_B + off, src);
        }
        asm volatile("cp.async.commit_group;" ::: "memory");
    };

    constexpr int NST = KTOT / BK;
    issue(0);
    issue(1);
    for (int c = 0; c < NST; ++c) {
        if (c + 1 < NST) asm volatile("cp.async.wait_group 1;" ::: "memory");
        else             asm volatile("cp.async.wait_group 0;" ::: "memory");
        __syncthreads();
        if (c + 2 < NST) issue(c + 2);

        const float2* As2 = (const float2*)(sm + (c % 3) * (STAGE_B / 4));
        const float2* Bs2 = (const float2*)((const char*)As2 + TILE_B);
        const float*  Bsf = (const float*)Bs2;

        #pragma unroll
        for (int ks = 0; ks < 4; ++ks) {
            const int kc = ks * 8 + tg;
            const int P  = ks * 4 + tg;
            uint32_t af[2][4], bf[8][2];
            #pragma unroll
            for (int mt = 0; mt < 2; ++mt) {
                const int r = wm0 + mt * 16 + gq;
                const float2 L1 = As2[r * 16 + (P ^ ((r & 3) << 2))];
                const float2 L2 = As2[(r + 8) * 16 + (P ^ ((r & 3) << 2))];
                af[mt][0] = __float_as_uint(L1.x);
                af[mt][1] = __float_as_uint(L2.x);
                af[mt][2] = __float_as_uint(L1.y);
                af[mt][3] = __float_as_uint(L2.y);
            }
            #pragma unroll
            for (int nt = 0; nt < 8; ++nt) {
                const int nr = wn0 + nt * 8 + gq;
                if (!BROW) {
                    const float2 Lb = Bs2[nr * 16 + (P ^ ((nr & 3) << 2))];
                    bf[nt][0] = __float_as_uint(Lb.x);
                    bf[nt][1] = __float_as_uint(Lb.y);
                } else {
                    bf[nt][0] = __float_as_uint(Bsf[kc * BNP + nr]);
                    bf[nt][1] = __float_as_uint(Bsf[(kc + 4) * BNP + nr]);
                }
            }
            #pragma unroll
            for (int mt = 0; mt < 2; ++mt)
                #pragma unroll
                for (int nt = 0; nt < 8; ++nt)
                    mma_tf32(acc[mt][nt], af[mt], bf[nt]);
        }
    }

    // ------------------------------------------------------------------ epi
    float inv2s2 = 0.f;
    if (BIAS) {
        const float s = fabsf(sigma[0]) + 1e-8f;
        inv2s2 = 1.0f / (2.0f * s * s);
    }

    #pragma unroll
    for (int mt = 0; mt < 2; ++mt) {
        #pragma unroll
        for (int h = 0; h < 2; ++h) {
            const int rn = r0 + wm0 + mt * 16 + gq + h * 8;
            float* orow = Og + (size_t)b * sO + (size_t)rn * ldO;
            const float npos = (float)rn * (1.0f / Nc);
            #pragma unroll
            for (int nt = 0; nt < 8; ++nt) {
                const int cg = c0 + wn0 + nt * 8;
                const float a0 = acc[mt][nt][h * 2 + 0];
                const float a1 = acc[mt][nt][h * 2 + 1];
                if (BIAS) {
                    const int cn = cg + 2 * tg;
                    const float d0 = npos - (float)(cn + 0) * (1.0f / Mc);
                    const float d1 = npos - (float)(cn + 1) * (1.0f / Mc);
                    float2 v = make_float2(a0 * 0.03125f - d0 * d0 * inv2s2,
                                           a1 * 0.03125f - d1 * d1 * inv2s2);
                    *(float2*)(orow + cn) = v;
                } else if (!BROW) {
                    *(float2*)(orow + cg + 2 * tg) = make_float2(a0, a1);
                } else {
                    // columns are permuted: pos 2tg -> logical tg, 2tg+1 -> tg+4
                    orow[cg + tg]     = a0;
                    orow[cg + tg + 4] = a1;
                }
            }
        }
    }
}

// ---------------------------------------------------------------------------
// Round to tf32 + k-pair permute (within 8-groups). One group per thread.
// ---------------------------------------------------------------------------
__global__ __launch_bounds__(256) void round_perm(
    const float* __restrict__ in, float* __restrict__ out)
{
    const size_t i = ((size_t)blockIdx.x * 256 + threadIdx.x) * 8;
    float4 a = *(const float4*)(in + i);
    float4 b = *(const float4*)(in + i + 4);
    float4 q0 = make_float4(tf32r(a.x), tf32r(b.x), tf32r(a.y), tf32r(b.y));
    float4 q1 = make_float4(tf32r(a.z), tf32r(b.z), tf32r(a.w), tf32r(b.w));
    *(float4*)(out + i)     = q0;
    *(float4*)(out + i + 4) = q1;
}

// ---------------------------------------------------------------------------
// Masked row softmax over M=2048; one block of 256 per (b,n) row.
// Thread t owns one 8-group (m = 8t..8t+7). Dual store: natural (unrounded)
// into attn (d_out), permuted+tf32-rounded into g_attnP for GEMM2.
// ---------------------------------------------------------------------------
__global__ __launch_bounds__(256) void softmax_rows(
    float* __restrict__ attn, const int* __restrict__ lens)
{
    const int row = blockIdx.x;
    const int b = row >> 10;
    const int len = lens[b];
    float* P  = attn    + (size_t)row * Mc;
    float* PP = g_attnP + (size_t)row * Mc;
    const int tid  = threadIdx.x;
    const int lane = tid & 31;
    const int wrp  = tid >> 5;
    const int j0   = tid * 8;

    __shared__ float red[8];

    float4 v0 = *(const float4*)(P + j0);
    float4 v1 = *(const float4*)(P + j0 + 4);
    float vals[8] = {
        (j0 + 0 < len) ? v0.x : -INFINITY, (j0 + 1 < len) ? v0.y : -INFINITY,
        (j0 + 2 < len) ? v0.z : -INFINITY, (j0 + 3 < len) ? v0.w : -INFINITY,
        (j0 + 4 < len) ? v1.x : -INFINITY, (j0 + 5 < len) ? v1.y : -INFINITY,
        (j0 + 6 < len) ? v1.z : -INFINITY, (j0 + 7 < len) ? v1.w : -INFINITY };

    float mx = vals[0];
    #pragma unroll
    for (int t = 1; t < 8; ++t) mx = fmaxf(mx, vals[t]);
    #pragma unroll
    for (int o = 16; o > 0; o >>= 1) mx = fmaxf(mx, __shfl_xor_sync(~0u, mx, o));
    if (lane == 0) red[wrp] = mx;
    __syncthreads();
    {
        float t = red[lane & 7];
        #pragma unroll
        for (int o = 4; o > 0; o >>= 1) t = fmaxf(t, __shfl_xor_sync(~0u, t, o));
        mx = t;
    }

    float sum = 0.0f;
    #pragma unroll
    for (int t = 0; t < 8; ++t) {
        const float e = (vals[t] == -INFINITY) ? 0.0f : __expf(vals[t] - mx);
        vals[t] = e;
        sum += e;
    }
    #pragma unroll
    for (int o = 16; o > 0; o >>= 1) sum += __shfl_xor_sync(~0u, sum, o);
    __syncthreads();
    if (lane == 0) red[wrp] = sum;
    __syncthreads();
    {
        float t = red[lane & 7];
        #pragma unroll
        for (int o = 4; o > 0; o >>= 1) t += __shfl_xor_sync(~0u, t, o);
        sum = t;
    }
    const float inv = 1.0f / sum;

    float w[8];
    #pragma unroll
    for (int t = 0; t < 8; ++t) w[t] = vals[t] * inv;

    *(float4*)(P + j0)     = make_float4(w[0], w[1], w[2], w[3]);
    *(float4*)(P + j0 + 4) = make_float4(w[4], w[5], w[6], w[7]);
    // permuted + rounded: positions [o0,o4,o1,o5, o2,o6,o3,o7]
    *(float4*)(PP + j0)     = make_float4(tf32r(w[0]), tf32r(w[4]), tf32r(w[1]), tf32r(w[5]));
    *(float4*)(PP + j0 + 4) = make_float4(tf32r(w[2]), tf32r(w[6]), tf32r(w[3]), tf32r(w[7]));
}

// ---------------------------------------------------------------------------
extern "C" void kernel_launch(void* const* d_in, const int* in_sizes, int n_in,
                              void* d_out, int out_size)
{
    const float* text  = (const float*)d_in[0];
    const float* audio = (const float*)d_in[1];
    const float* sigma = (const float*)d_in[2];
    const int*   lens  = (const int*)d_in[3];

    float* enhanced = (float*)d_out;                    // B*N*D
    float* attn     = enhanced + (size_t)Bc * Nc * Dc;  // B*N*M (scores scratch)

    void *audioR_p = nullptr, *textR_p = nullptr, *attnP_p = nullptr;
    cudaGetSymbolAddress(&audioR_p, g_audioR);
    cudaGetSymbolAddress(&textR_p,  g_textR);
    cudaGetSymbolAddress(&attnP_p,  g_attnP);

    constexpr int SM1 = 3 * (TILE_B + TILE_B);    // 98304 B
    constexpr int SM2 = 3 * (TILE_B + BROW_B);    // 101376 B
    cudaFuncSetAttribute(tc_gemm<Dc, true, false>,
                         cudaFuncAttributeMaxDynamicSharedMemorySize, SM1);
    cudaFuncSetAttribute(tc_gemm<Mc, false, true>,
                         cudaFuncAttributeMaxDynamicSharedMemorySize, SM2);

    round_perm<<<(Bc * Nc * Dc) / 2048, 256>>>(text,  (float*)textR_p);
    round_perm<<<(Bc * Mc * Dc) / 2048, 256>>>(audio, (float*)audioR_p);

    // GEMM1: scores = textR . audioR^T (+bias) -> attn
    tc_gemm<Dc, true, false><<<dim3(Mc / 128, Nc / 128, Bc), 256, SM1>>>(
        (const float*)textR_p, (const float*)audioR_p, attn,
        (size_t)Nc * Dc, (size_t)Mc * Dc, (size_t)Nc * Mc,
        Dc, Dc, Mc, sigma);

    softmax_rows<<<Bc * Nc, 256>>>(attn, lens);

    // GEMM2: enhanced = attnP . audioR (B row-major-by-k, natural m rows;
    // permuted d columns un-permuted in epilogue)
    tc_gemm<Mc, false, true><<<dim3(Dc / 128, Nc / 128, Bc), 256, SM2>>>(
        (const float*)attnP_p, (const float*)audioR_p, enhanced,
        (size_t)Nc * Mc, (size_t)Mc * Dc, (size_t)Nc * Dc,
        Mc, Dc, Dc, nullptr);
}

// round 8
// speedup vs baseline: 1.0451x; 1.0451x over previous
#include <cuda_runtime.h>
#include <math.h>
#include <stdint.h>

#define Bc 8
#define Nc 1024
#define Mc 2048
#define Dc 1024

// Scratch (allocation-free rule).
// *P buffers are k-pair-PERMUTED within 8-groups: logical offset o (0..7)
// lives at position 2*(o&3)+(o>>2)  ->  [o0,o4,o1,o5,o2,o6,o3,o7].
__device__ float g_textP [(size_t)Bc * Nc * Dc];   // [b][n][d_perm], tf32
__device__ float g_audioP[(size_t)Bc * Mc * Dc];   // [b][m][d_perm], tf32
__device__ float g_audioR[(size_t)Bc * Mc * Dc];   // [b][m][d] natural, tf32

__device__ __forceinline__ float tf32r(float x) {
    uint32_t u;
    asm("cvt.rna.tf32.f32 %0, %1;" : "=r"(u) : "f"(x));
    return __uint_as_float(u);
}
__device__ __forceinline__ void cp_async16(uint32_t dst, const void* src) {
    asm volatile("cp.async.cg.shared.global [%0], [%1], 16;" :: "r"(dst), "l"(src) : "memory");
}
__device__ __forceinline__ void mma_tf32(float* c, const uint32_t* a, const uint32_t* b) {
    asm volatile(
        "mma.sync.aligned.m16n8k8.row.col.f32.tf32.tf32.f32 "
        "{%0,%1,%2,%3}, {%4,%5,%6,%7}, {%8,%9}, {%0,%1,%2,%3};"
        : "+f"(c[0]), "+f"(c[1]), "+f"(c[2]), "+f"(c[3])
        : "r"(a[0]), "r"(a[1]), "r"(a[2]), "r"(a[3]), "r"(b[0]), "r"(b[1]));
}

#define BM 128
#define BN 128
#define BK 32

// Permuted tile (GEMM1 A and B): 128 rows x 16 f2, XOR swizzle on f2 index.
#define TILE_B    16384
// GEMM2: A natural K-major padded, B row-major-by-k padded
#define AKP       36
#define A_NAT_B   (128 * AKP * 4)     // 18432
#define BNP       136
#define BROW_B    (32 * BNP * 4)      // 17408

// ---------------------------------------------------------------------------
// tf32 tensor-core GEMM, 128x128 CTA tile, 8 warps (32x64 warp tile),
// 3-stage cp.async pipeline, one __syncthreads per K-stage.
//  PERM=true : GEMM1 — A,B both K-major pair-permuted global, f2 swizzled smem
//  PERM=false: GEMM2 — A natural K-major (scalar frags), B [k][col] natural
// ---------------------------------------------------------------------------
template<int KTOT, bool BIAS, bool PERM>
__global__ __launch_bounds__(256, 2) void tc_gemm(
    const float* __restrict__ Ag, const float* __restrict__ Bg,
    float* __restrict__ Og,
    size_t sA, size_t sB, size_t sO,
    int ldA, int ldB, int ldO,
    const float* __restrict__ sigma)
{
    constexpr uint32_t A_BYTES = PERM ? TILE_B : A_NAT_B;
    constexpr uint32_t B_BYTES = PERM ? TILE_B : BROW_B;
    constexpr uint32_t STAGE_B = A_BYTES + B_BYTES;

    extern __shared__ float sm[];
    const uint32_t smemU = (uint32_t)__cvta_generic_to_shared(sm);
    const int tid  = threadIdx.x;
    const int lane = tid & 31;
    const int wid  = tid >> 5;
    const int wm0  = (wid & 3) * 32;
    const int wn0  = (wid >> 2) * 64;
    const int gq   = lane >> 2;
    const int tg   = lane & 3;

    const int b  = blockIdx.z;
    const int r0 = blockIdx.y * BM;
    const int c0 = blockIdx.x * BN;

    const float* Ab = Ag + (size_t)b * sA + (size_t)r0 * ldA;
    const float* Bb = Bg + (size_t)b * sB + (PERM ? (size_t)c0 * ldB : (size_t)c0);

    float acc[2][8][4];
    #pragma unroll
    for (int mt = 0; mt < 2; ++mt)
        #pragma unroll
        for (int nt = 0; nt < 8; ++nt)
            #pragma unroll
            for (int r = 0; r < 4; ++r) acc[mt][nt][r] = 0.0f;

    auto issue = [&](int c) {
        const int s  = c % 3;
        const int k0 = c * BK;
        #pragma unroll
        for (int i = 0; i < 8; ++i) {
            const int q   = tid + i * 256;        // 0..2047
            const int isB = q >> 10;
            const int qq  = q & 1023;
            const float* src;
            uint32_t off;
            if (PERM) {
                const int row = qq >> 3, j = qq & 7;
                src = (isB ? Bb : Ab) + (size_t)row * (isB ? ldB : ldA) + k0 + j * 4;
                off = (isB ? TILE_B : 0u)
                    + (uint32_t)(row * 128 + (((2 * j) ^ ((row & 3) << 2)) << 3));
            } else if (!isB) {
                const int row = qq >> 3, j = qq & 7;
                src = Ab + (size_t)row * ldA + k0 + j * 4;
                off = (uint32_t)(row * (AKP * 4) + j * 16);
            } else {
                const int kr = qq >> 5, jc = qq & 31;
                src = Bb + (size_t)(k0 + kr) * ldB + jc * 4;
                off = A_BYTES + (uint32_t)(kr * (BNP * 4) + jc * 16);
            }
            cp_async16(smemU + s * STAGE_B + off, src);
        }
        asm volatile("cp.async.commit_group;" ::: "memory");
    };

    constexpr int NST = KTOT / BK;
    issue(0);
    issue(1);
    for (int c = 0; c < NST; ++c) {
        if (c + 1 < NST) asm volatile("cp.async.wait_group 1;" ::: "memory");
        else             asm volatile("cp.async.wait_group 0;" ::: "memory");
        __syncthreads();
        if (c + 2 < NST) issue(c + 2);

        const float* Asf = sm + (c % 3) * (STAGE_B / 4);
        const float2* As2 = (const float2*)Asf;
        const float* Bsf = Asf + A_BYTES / 4;
        const float2* Bs2 = (const float2*)Bsf;

        #pragma unroll
        for (int ks = 0; ks < 4; ++ks) {
            const int kc = ks * 8 + tg;
            const int P  = ks * 4 + tg;
            uint32_t af[2][4], bf[8][2];
            #pragma unroll
            for (int mt = 0; mt < 2; ++mt) {
                const int r = wm0 + mt * 16 + gq;
                if (PERM) {
                    const float2 L1 = As2[r * 16 + (P ^ ((r & 3) << 2))];
                    const float2 L2 = As2[(r + 8) * 16 + (P ^ ((r & 3) << 2))];
                    af[mt][0] = __float_as_uint(L1.x);
                    af[mt][1] = __float_as_uint(L2.x);
                    af[mt][2] = __float_as_uint(L1.y);
                    af[mt][3] = __float_as_uint(L2.y);
                } else {
                    af[mt][0] = __float_as_uint(Asf[r * AKP + kc]);
                    af[mt][1] = __float_as_uint(Asf[(r + 8) * AKP + kc]);
                    af[mt][2] = __float_as_uint(Asf[r * AKP + kc + 4]);
                    af[mt][3] = __float_as_uint(Asf[(r + 8) * AKP + kc + 4]);
                }
            }
            #pragma unroll
            for (int nt = 0; nt < 8; ++nt) {
                const int nr = wn0 + nt * 8 + gq;
                if (PERM) {
                    const float2 Lb = Bs2[nr * 16 + (P ^ ((nr & 3) << 2))];
                    bf[nt][0] = __float_as_uint(Lb.x);
                    bf[nt][1] = __float_as_uint(Lb.y);
                } else {
                    bf[nt][0] = __float_as_uint(Bsf[kc * BNP + nr]);
                    bf[nt][1] = __float_as_uint(Bsf[(kc + 4) * BNP + nr]);
                }
            }
            #pragma unroll
            for (int mt = 0; mt < 2; ++mt)
                #pragma unroll
                for (int nt = 0; nt < 8; ++nt)
                    mma_tf32(acc[mt][nt], af[mt], bf[nt]);
        }
    }

    // ------------------------------------------------------------------ epi
    float inv2s2 = 0.f;
    if (BIAS) {
        const float s = fabsf(sigma[0]) + 1e-8f;
        inv2s2 = 1.0f / (2.0f * s * s);
    }

    #pragma unroll
    for (int mt = 0; mt < 2; ++mt) {
        #pragma unroll
        for (int h = 0; h < 2; ++h) {
            const int rn = r0 + wm0 + mt * 16 + gq + h * 8;
            float* orow = Og + (size_t)b * sO + (size_t)rn * ldO;
            const float npos = (float)rn * (1.0f / Nc);
            #pragma unroll
            for (int nt = 0; nt < 8; ++nt) {
                const int cn = c0 + wn0 + nt * 8 + 2 * tg;
                float2 v = make_float2(acc[mt][nt][h * 2 + 0],
                                       acc[mt][nt][h * 2 + 1]);
                if (BIAS) {
                    const float d0 = npos - (float)(cn + 0) * (1.0f / Mc);
                    const float d1 = npos - (float)(cn + 1) * (1.0f / Mc);
                    v.x = v.x * 0.03125f - d0 * d0 * inv2s2;
                    v.y = v.y * 0.03125f - d1 * d1 * inv2s2;
                }
                *(float2*)(orow + cn) = v;
            }
        }
    }
}

// ---------------------------------------------------------------------------
// text -> g_textP: round to tf32 + k-pair permute. One 8-group per thread.
// ---------------------------------------------------------------------------
__global__ __launch_bounds__(256) void prep_text(const float* __restrict__ in)
{
    const size_t i = ((size_t)blockIdx.x * 256 + threadIdx.x) * 8;
    float4 a = *(const float4*)(in + i);
    float4 b = *(const float4*)(in + i + 4);
    *(float4*)(g_textP + i)     = make_float4(tf32r(a.x), tf32r(b.x), tf32r(a.y), tf32r(b.y));
    *(float4*)(g_textP + i + 4) = make_float4(tf32r(a.z), tf32r(b.z), tf32r(a.w), tf32r(b.w));
}

// ---------------------------------------------------------------------------
// audio -> g_audioR (natural, rounded) + g_audioP (permuted, rounded).
// ---------------------------------------------------------------------------
__global__ __launch_bounds__(256) void prep_audio(const float* __restrict__ in)
{
    const size_t i = ((size_t)blockIdx.x * 256 + threadIdx.x) * 8;
    float4 a = *(const float4*)(in + i);
    float4 b = *(const float4*)(in + i + 4);
    a.x = tf32r(a.x); a.y = tf32r(a.y); a.z = tf32r(a.z); a.w = tf32r(a.w);
    b.x = tf32r(b.x); b.y = tf32r(b.y); b.z = tf32r(b.z); b.w = tf32r(b.w);
    *(float4*)(g_audioR + i)     = a;
    *(float4*)(g_audioR + i + 4) = b;
    *(float4*)(g_audioP + i)     = make_float4(a.x, b.x, a.y, b.y);
    *(float4*)(g_audioP + i + 4) = make_float4(a.z, b.z, a.w, b.w);
}

// ---------------------------------------------------------------------------
// Masked row softmax over M=2048; one block of 256 per (b,n) row.
// float4 I/O, warp-shuffle reductions, __expf, tf32-rounded in-place store.
// ---------------------------------------------------------------------------
__global__ __launch_bounds__(256) void softmax_rows(
    float* __restrict__ attn, const int* __restrict__ lens)
{
    const int row = blockIdx.x;
    const int b = row >> 10;
    const int len = lens[b];
    float* P = attn + (size_t)row * Mc;
    const int tid  = threadIdx.x;
    const int lane = tid & 31;
    const int wrp  = tid >> 5;

    __shared__ float red[8];

    float4 v0 = *(const float4*)(P + tid * 4);
    float4 v1 = *(const float4*)(P + 1024 + tid * 4);
    const int j0 = tid * 4, j1 = 1024 + tid * 4;

    float vals[8] = {
        (j0 + 0 < len) ? v0.x : -INFINITY, (j0 + 1 < len) ? v0.y : -INFINITY,
        (j0 + 2 < len) ? v0.z : -INFINITY, (j0 + 3 < len) ? v0.w : -INFINITY,
        (j1 + 0 < len) ? v1.x : -INFINITY, (j1 + 1 < len) ? v1.y : -INFINITY,
        (j1 + 2 < len) ? v1.z : -INFINITY, (j1 + 3 < len) ? v1.w : -INFINITY };

    float mx = vals[0];
    #pragma unroll
    for (int t = 1; t < 8; ++t) mx = fmaxf(mx, vals[t]);
    #pragma unroll
    for (int o = 16; o > 0; o >>= 1) mx = fmaxf(mx, __shfl_xor_sync(~0u, mx, o));
    if (lane == 0) red[wrp] = mx;
    __syncthreads();
    {
        float t = red[lane & 7];
        #pragma unroll
        for (int o = 4; o > 0; o >>= 1) t = fmaxf(t, __shfl_xor_sync(~0u, t, o));
        mx = t;
    }

    float sum = 0.0f;
    #pragma unroll
    for (int t = 0; t < 8; ++t) {
        const float e = (vals[t] == -INFINITY) ? 0.0f : __expf(vals[t] - mx);
        vals[t] = e;
        sum += e;
    }
    #pragma unroll
    for (int o = 16; o > 0; o >>= 1) sum += __shfl_xor_sync(~0u, sum, o);
    __syncthreads();
    if (lane == 0) red[wrp] = sum;
    __syncthreads();
    {
        float t = red[lane & 7];
        #pragma unroll
        for (int o = 4; o > 0; o >>= 1) t += __shfl_xor_sync(~0u, t, o);
        sum = t;
    }
    const float inv = 1.0f / sum;

    v0.x = tf32r(vals[0] * inv); v0.y = tf32r(vals[1] * inv);
    v0.z = tf32r(vals[2] * inv); v0.w = tf32r(vals[3] * inv);
    v1.x = tf32r(vals[4] * inv); v1.y = tf32r(vals[5] * inv);
    v1.z = tf32r(vals[6] * inv); v1.w = tf32r(vals[7] * inv);
    *(float4*)(P + tid * 4) = v0;
    *(float4*)(P + 1024 + tid * 4) = v1;
}

// ---------------------------------------------------------------------------
extern "C" void kernel_launch(void* const* d_in, const int* in_sizes, int n_in,
                              void* d_out, int out_size)
{
    const float* text  = (const float*)d_in[0];
    const float* audio = (const float*)d_in[1];
    const float* sigma = (const float*)d_in[2];
    const int*   lens  = (const int*)d_in[3];

    float* enhanced = (float*)d_out;                    // B*N*D
    float* attn     = enhanced + (size_t)Bc * Nc * Dc;  // B*N*M (scores scratch)

    void *textP_p = nullptr, *audioP_p = nullptr, *audioR_p = nullptr;
    cudaGetSymbolAddress(&textP_p,  g_textP);
    cudaGetSymbolAddress(&audioP_p, g_audioP);
    cudaGetSymbolAddress(&audioR_p, g_audioR);

    constexpr int SM1 = 3 * (TILE_B + TILE_B);     // 98304 B
    constexpr int SM2 = 3 * (A_NAT_B + BROW_B);    // 107520 B
    cudaFuncSetAttribute(tc_gemm<Dc, true, true>,
                         cudaFuncAttributeMaxDynamicSharedMemorySize, SM1);
    cudaFuncSetAttribute(tc_gemm<Mc, false, false>,
                         cudaFuncAttributeMaxDynamicSharedMemorySize, SM2);

    prep_text <<<(Bc * Nc * Dc) / 2048, 256>>>(text);
    prep_audio<<<(Bc * Mc * Dc) / 2048, 256>>>(audio);

    // GEMM1: scores = textP . audioP^T (+bias) -> attn   (permuted operands)
    tc_gemm<Dc, true, true><<<dim3(Mc / 128, Nc / 128, Bc), 256, SM1>>>(
        (const float*)textP_p, (const float*)audioP_p, attn,
        (size_t)Nc * Dc, (size_t)Mc * Dc, (size_t)Nc * Mc,
        Dc, Dc, Mc, sigma);

    softmax_rows<<<Bc * Nc, 256>>>(attn, lens);

    // GEMM2: enhanced = attn . audioR  (natural layouts, R4 path)
    tc_gemm<Mc, false, false><<<dim3(Dc / 128, Nc / 128, Bc), 256, SM2>>>(
        attn, (const float*)audioR_p, enhanced,
        (size_t)Nc * Mc, (size_t)Mc * Dc, (size_t)Nc * Dc,
        Mc, Dc, Dc, nullptr);
}

// round 10
// speedup vs baseline: 1.5302x; 1.4641x over previous
#include <cuda_runtime.h>
#include <cuda_fp16.h>
#include <math.h>
#include <stdint.h>

#define Bc 8
#define Nc 1024
#define Mc 2048
#define Dc 1024

// fp16 scratch (allocation-free rule), all K-major for their GEMM use
__device__ __half g_textH  [(size_t)Bc * Nc * Dc];   // [b][n][d]
__device__ __half g_audioH [(size_t)Bc * Mc * Dc];   // [b][m][d]
__device__ __half g_audioTH[(size_t)Bc * Dc * Mc];   // [b][d][m]
__device__ __half g_attnH  [(size_t)Bc * Nc * Mc];   // [b][n][m]

__device__ __forceinline__ void cp_async16(uint32_t dst, const void* src) {
    asm volatile("cp.async.cg.shared.global [%0], [%1], 16;" :: "r"(dst), "l"(src) : "memory");
}
__device__ __forceinline__ void mma_f16(float* c, const uint32_t* a, const uint32_t* b) {
    asm volatile(
        "mma.sync.aligned.m16n8k16.row.col.f32.f16.f16.f32 "
        "{%0,%1,%2,%3}, {%4,%5,%6,%7}, {%8,%9}, {%0,%1,%2,%3};"
        : "+f"(c[0]), "+f"(c[1]), "+f"(c[2]), "+f"(c[3])
        : "r"(a[0]), "r"(a[1]), "r"(a[2]), "r"(a[3]), "r"(b[0]), "r"(b[1]));
}

#define BM 128
#define BN 128
#define BK 32          // K chunk per stage (halfs)
#define AS 40          // smem row stride in halfs (80 B): bank-conflict-free
#define TILE_HB (128 * AS * 2)          // 10240 B per operand tile
#define STAGE_B (2 * TILE_HB)           // 20480 B per stage
#define SMEM_B  (3 * STAGE_B)           // 61440 B

// ---------------------------------------------------------------------------
// fp16 tensor-core GEMM: D[128x128] = A[128xK] . B[128xK]^T per CTA tile.
// A rows = out rows, B rows = out cols, both K-major fp16.
// 8 warps (32x64 warp tile), m16n8k16, 3-stage cp.async pipeline.
// BIAS fuses /sqrt(D) + Gaussian positional bias (GEMM1 -> scores).
// ---------------------------------------------------------------------------
template<int KTOT, bool BIAS>
__global__ __launch_bounds__(256, 2) void tc_gemm(
    const __half* __restrict__ Ag, const __half* __restrict__ Bg,
    float* __restrict__ Og,
    size_t sA, size_t sB, size_t sO,
    int ldA, int ldB, int ldO,
    const float* __restrict__ sigma)
{
    extern __shared__ char smc[];
    const uint32_t smemU = (uint32_t)__cvta_generic_to_shared(smc);
    const int tid  = threadIdx.x;
    const int lane = tid & 31;
    const int wid  = tid >> 5;
    const int wm0  = (wid & 3) * 32;
    const int wn0  = (wid >> 2) * 64;
    const int gq   = lane >> 2;
    const int tg   = lane & 3;

    const int b  = blockIdx.z;
    const int r0 = blockIdx.y * BM;
    const int c0 = blockIdx.x * BN;

    const __half* Ab = Ag + (size_t)b * sA + (size_t)r0 * ldA;
    const __half* Bb = Bg + (size_t)b * sB + (size_t)c0 * ldB;

    float acc[2][8][4];
    #pragma unroll
    for (int mt = 0; mt < 2; ++mt)
        #pragma unroll
        for (int nt = 0; nt < 8; ++nt)
            #pragma unroll
            for (int r = 0; r < 4; ++r) acc[mt][nt][r] = 0.0f;

    auto issue = [&](int c) {
        const int s  = c % 3;
        const int k0 = c * BK;
        #pragma unroll
        for (int i = 0; i < 4; ++i) {
            const int q   = tid + i * 256;     // 0..1023
            const int isB = q >> 9;
            const int qq  = q & 511;
            const int row = qq >> 2;
            const int seg = qq & 3;            // 16B segment within 64B row
            const char* src = (const char*)((isB ? Bb : Ab)
                            + (size_t)row * (isB ? ldB : ldA) + k0) + seg * 16;
            const uint32_t off = (isB ? TILE_HB : 0u)
                               + (uint32_t)(row * (AS * 2) + seg * 16);
            cp_async16(smemU + s * STAGE_B + off, src);
        }
        asm volatile("cp.async.commit_group;" ::: "memory");
    };

    constexpr int NST = KTOT / BK;
    issue(0);
    issue(1);
    for (int c = 0; c < NST; ++c) {
        if (c + 1 < NST) asm volatile("cp.async.wait_group 1;" ::: "memory");
        else             asm volatile("cp.async.wait_group 0;" ::: "memory");
        __syncthreads();
        if (c + 2 < NST) issue(c + 2);

        const __half* Asf = (const __half*)(smc + (c % 3) * STAGE_B);
        const __half* Bsf = (const __half*)(smc + (c % 3) * STAGE_B + TILE_HB);

        #pragma unroll
        for (int ks = 0; ks < 2; ++ks) {
            const int kc = ks * 16 + 2 * tg;
            uint32_t af[2][4], bf[8][2];
            #pragma unroll
            for (int mt = 0; mt < 2; ++mt) {
                const int r = wm0 + mt * 16 + gq;
                af[mt][0] = *(const uint32_t*)&Asf[r * AS + kc];
                af[mt][1] = *(const uint32_t*)&Asf[(r + 8) * AS + kc];
                af[mt][2] = *(const uint32_t*)&Asf[r * AS + kc + 8];
                af[mt][3] = *(const uint32_t*)&Asf[(r + 8) * AS + kc + 8];
            }
            #pragma unroll
            for (int nt = 0; nt < 8; ++nt) {
                const int nr = wn0 + nt * 8 + gq;
                bf[nt][0] = *(const uint32_t*)&Bsf[nr * AS + kc];
                bf[nt][1] = *(const uint32_t*)&Bsf[nr * AS + kc + 8];
            }
            #pragma unroll
            for (int mt = 0; mt < 2; ++mt)
                #pragma unroll
                for (int nt = 0; nt < 8; ++nt)
                    mma_f16(acc[mt][nt], af[mt], bf[nt]);
        }
    }

    // ------------------------------------------------------------------ epi
    float inv2s2 = 0.f;
    if (BIAS) {
        const float s = fabsf(sigma[0]) + 1e-8f;
        inv2s2 = 1.0f / (2.0f * s * s);
    }

    #pragma unroll
    for (int mt = 0; mt < 2; ++mt) {
        #pragma unroll
        for (int h = 0; h < 2; ++h) {
            const int rn = r0 + wm0 + mt * 16 + gq + h * 8;
            float* orow = Og + (size_t)b * sO + (size_t)rn * ldO;
            const float npos = (float)rn * (1.0f / Nc);
            #pragma unroll
            for (int nt = 0; nt < 8; ++nt) {
                const int cn = c0 + wn0 + nt * 8 + 2 * tg;
                float2 v = make_float2(acc[mt][nt][h * 2 + 0],
                                       acc[mt][nt][h * 2 + 1]);
                if (BIAS) {
                    const float d0 = npos - (float)(cn + 0) * (1.0f / Mc);
                    const float d1 = npos - (float)(cn + 1) * (1.0f / Mc);
                    v.x = v.x * 0.03125f - d0 * d0 * inv2s2;
                    v.y = v.y * 0.03125f - d1 * d1 * inv2s2;
                }
                *(float2*)(orow + cn) = v;
            }
        }
    }
}

// ---------------------------------------------------------------------------
// fp32 -> fp16 streaming convert (8 elements/thread)
// ---------------------------------------------------------------------------
__global__ __launch_bounds__(256) void cvt_h(
    const float* __restrict__ in, __half* __restrict__ out)
{
    const size_t i = ((size_t)blockIdx.x * 256 + threadIdx.x) * 8;
    float4 a = *(const float4*)(in + i);
    float4 b = *(const float4*)(in + i + 4);
    __half2 h[4] = {
        __floats2half2_rn(a.x, a.y), __floats2half2_rn(a.z, a.w),
        __floats2half2_rn(b.x, b.y), __floats2half2_rn(b.z, b.w) };
    *(uint4*)(out + i) = *(const uint4*)h;
}

// ---------------------------------------------------------------------------
// audio [b][m][d] fp32 -> g_audioTH [b][d][m] fp16 (32x32 smem tile transpose)
// ---------------------------------------------------------------------------
__global__ __launch_bounds__(256) void transpose_h(const float* __restrict__ audio)
{
    __shared__ __half t[32][33];
    const int b  = blockIdx.z;
    const int m0 = blockIdx.x * 32;
    const int d0 = blockIdx.y * 32;
    const int tx = threadIdx.x & 31;
    const int ty = threadIdx.x >> 5;    // 0..7

    const float* src = audio + (size_t)b * Mc * Dc;
    #pragma unroll
    for (int i = 0; i < 4; ++i)
        t[ty + i * 8][tx] = __float2half_rn(src[(size_t)(m0 + ty + i * 8) * Dc + d0 + tx]);
    __syncthreads();
    __half* dst = g_audioTH + (size_t)b * Dc * Mc;
    #pragma unroll
    for (int i = 0; i < 4; ++i)
        dst[(size_t)(d0 + ty + i * 8) * Mc + m0 + tx] = t[tx][ty + i * 8];
}

// ---------------------------------------------------------------------------
// Masked row softmax over M=2048; one block of 256 per (b,n) row.
// Stores: fp32 (unrounded) in place (d_out) + fp16 copy for GEMM2.
// ---------------------------------------------------------------------------
__global__ __launch_bounds__(256) void softmax_rows(
    float* __restrict__ attn, const int* __restrict__ lens)
{
    const int row = blockIdx.x;
    const int b = row >> 10;
    const int len = lens[b];
    float*  P  = attn    + (size_t)row * Mc;
    __half* PH = g_attnH + (size_t)row * Mc;
    const int tid  = threadIdx.x;
    const int lane = tid & 31;
    const int wrp  = tid >> 5;
    const int j0   = tid * 8;

    __shared__ float red[8];

    float4 v0 = *(const float4*)(P + j0);
    float4 v1 = *(const float4*)(P + j0 + 4);
    float vals[8] = {
        (j0 + 0 < len) ? v0.x : -INFINITY, (j0 + 1 < len) ? v0.y : -INFINITY,
        (j0 + 2 < len) ? v0.z : -INFINITY, (j0 + 3 < len) ? v0.w : -INFINITY,
        (j0 + 4 < len) ? v1.x : -INFINITY, (j0 + 5 < len) ? v1.y : -INFINITY,
        (j0 + 6 < len) ? v1.z : -INFINITY, (j0 + 7 < len) ? v1.w : -INFINITY };

    float mx = vals[0];
    #pragma unroll
    for (int t = 1; t < 8; ++t) mx = fmaxf(mx, vals[t]);
    #pragma unroll
    for (int o = 16; o > 0; o >>= 1) mx = fmaxf(mx, __shfl_xor_sync(~0u, mx, o));
    if (lane == 0) red[wrp] = mx;
    __syncthreads();
    {
        float t = red[lane & 7];
        #pragma unroll
        for (int o = 4; o > 0; o >>= 1) t = fmaxf(t, __shfl_xor_sync(~0u, t, o));
        mx = t;
    }

    float sum = 0.0f;
    #pragma unroll
    for (int t = 0; t < 8; ++t) {
        const float e = (vals[t] == -INFINITY) ? 0.0f : __expf(vals[t] - mx);
        vals[t] = e;
        sum += e;
    }
    #pragma unroll
    for (int o = 16; o > 0; o >>= 1) sum += __shfl_xor_sync(~0u, sum, o);
    __syncthreads();
    if (lane == 0) red[wrp] = sum;
    __syncthreads();
    {
        float t = red[lane & 7];
        #pragma unroll
        for (int o = 4; o > 0; o >>= 1) t += __shfl_xor_sync(~0u, t, o);
        sum = t;
    }
    const float inv = 1.0f / sum;

    float w[8];
    #pragma unroll
    for (int t = 0; t < 8; ++t) w[t] = vals[t] * inv;

    *(float4*)(P + j0)     = make_float4(w[0], w[1], w[2], w[3]);
    *(float4*)(P + j0 + 4) = make_float4(w[4], w[5], w[6], w[7]);

    __half2 h[4] = {
        __floats2half2_rn(w[0], w[1]), __floats2half2_rn(w[2], w[3]),
        __floats2half2_rn(w[4], w[5]), __floats2half2_rn(w[6], w[7]) };
    *(uint4*)(PH + j0) = *(const uint4*)h;
}

// ---------------------------------------------------------------------------
extern "C" void kernel_launch(void* const* d_in, const int* in_sizes, int n_in,
                              void* d_out, int out_size)
{
    const float* text  = (const float*)d_in[0];
    const float* audio = (const float*)d_in[1];
    const float* sigma = (const float*)d_in[2];
    const int*   lens  = (const int*)d_in[3];

    float* enhanced = (float*)d_out;                    // B*N*D
    float* attn     = enhanced + (size_t)Bc * Nc * Dc;  // B*N*M (scores scratch)

    void *textH_p = nullptr, *audioH_p = nullptr, *audioTH_p = nullptr, *attnH_p = nullptr;
    cudaGetSymbolAddress(&textH_p,   g_textH);
    cudaGetSymbolAddress(&audioH_p,  g_audioH);
    cudaGetSymbolAddress(&audioTH_p, g_audioTH);
    cudaGetSymbolAddress(&attnH_p,   g_attnH);

    cudaFuncSetAttribute(tc_gemm<Dc, true>,
                         cudaFuncAttributeMaxDynamicSharedMemorySize, SMEM_B);
    cudaFuncSetAttribute(tc_gemm<Mc, false>,
                         cudaFuncAttributeMaxDynamicSharedMemorySize, SMEM_B);

    cvt_h<<<(Bc * Nc * Dc) / 2048, 256>>>(text,  (__half*)textH_p);
    cvt_h<<<(Bc * Mc * Dc) / 2048, 256>>>(audio, (__half*)audioH_p);
    transpose_h<<<dim3(Mc / 32, Dc / 32, Bc), 256>>>(audio);

    // GEMM1: scores = textH . audioH^T (+bias) -> attn
    tc_gemm<Dc, true><<<dim3(Mc / 128, Nc / 128, Bc), 256, SMEM_B>>>(
        (const __half*)textH_p, (const __half*)audioH_p, attn,
        (size_t)Nc * Dc, (size_t)Mc * Dc, (size_t)Nc * Mc,
        Dc, Dc, Mc, sigma);

    softmax_rows<<<Bc * Nc, 256>>>(attn, lens);

    // GEMM2: enhanced = attnH . audioTH^T  (K-major over m on both sides)
    tc_gemm<Mc, false><<<dim3(Dc / 128, Nc / 128, Bc), 256, SMEM_B>>>(
        (const __half*)attnH_p, (const __half*)audioTH_p, enhanced,
        (size_t)Nc * Mc, (size_t)Dc * Mc, (size_t)Nc * Dc,
        Mc, Mc, Dc, nullptr);
}

// round 11
// speedup vs baseline: 1.6834x; 1.1002x over previous
#include <cuda_runtime.h>
#include <cuda_fp16.h>
#include <math.h>
#include <stdint.h>

#define Bc 8
#define Nc 1024
#define Mc 2048
#define Dc 1024

// fp16 scratch (allocation-free rule), all K-major for their GEMM use
__device__ __half g_textH  [(size_t)Bc * Nc * Dc];   // [b][n][d]
__device__ __half g_audioH [(size_t)Bc * Mc * Dc];   // [b][m][d]
__device__ __half g_audioTH[(size_t)Bc * Dc * Mc];   // [b][d][m]
__device__ __half g_attnH  [(size_t)Bc * Nc * Mc];   // [b][n][m]

__device__ __forceinline__ void cp_async16(uint32_t dst, const void* src) {
    asm volatile("cp.async.cg.shared.global [%0], [%1], 16;" :: "r"(dst), "l"(src) : "memory");
}
__device__ __forceinline__ void mma_f16(float* c, const uint32_t* a, const uint32_t* b) {
    asm volatile(
        "mma.sync.aligned.m16n8k16.row.col.f32.f16.f16.f32 "
        "{%0,%1,%2,%3}, {%4,%5,%6,%7}, {%8,%9}, {%0,%1,%2,%3};"
        : "+f"(c[0]), "+f"(c[1]), "+f"(c[2]), "+f"(c[3])
        : "r"(a[0]), "r"(a[1]), "r"(a[2]), "r"(a[3]), "r"(b[0]), "r"(b[1]));
}
__device__ __forceinline__ void ldsm_x4(uint32_t* r, uint32_t addr) {
    asm volatile("ldmatrix.sync.aligned.m8n8.x4.shared.b16 {%0,%1,%2,%3}, [%4];"
        : "=r"(r[0]), "=r"(r[1]), "=r"(r[2]), "=r"(r[3]) : "r"(addr));
}

#define BM 128
#define BN 128
#define BK 32          // K chunk per stage (halfs)
#define AS 40          // smem row stride in halfs (80 B): LDSM conflict-free
#define TILE_HB (128 * AS * 2)          // 10240 B per operand tile
#define STAGE_B (2 * TILE_HB)           // 20480 B per stage
#define NSTAGE  4
#define SMEM_B  (NSTAGE * STAGE_B)      // 81920 B

// ---------------------------------------------------------------------------
// fp16 tensor-core GEMM: D[128x128] = A[128xK] . B[128xK]^T per CTA tile.
// 8 warps (32x64 warp tile), m16n8k16, ldmatrix fragments,
// 4-stage cp.async pipeline. BIAS fuses /sqrt(D) + Gaussian bias (GEMM1).
// ---------------------------------------------------------------------------
template<int KTOT, bool BIAS>
__global__ __launch_bounds__(256, 2) void tc_gemm(
    const __half* __restrict__ Ag, const __half* __restrict__ Bg,
    float* __restrict__ Og,
    size_t sA, size_t sB, size_t sO,
    int ldA, int ldB, int ldO,
    const float* __restrict__ sigma)
{
    extern __shared__ char smc[];
    const uint32_t smemU = (uint32_t)__cvta_generic_to_shared(smc);
    const int tid  = threadIdx.x;
    const int lane = tid & 31;
    const int wid  = tid >> 5;
    const int wm0  = (wid & 3) * 32;
    const int wn0  = (wid >> 2) * 64;
    const int gq   = lane >> 2;
    const int tg   = lane & 3;

    const int b  = blockIdx.z;
    const int r0 = blockIdx.y * BM;
    const int c0 = blockIdx.x * BN;

    const __half* Ab = Ag + (size_t)b * sA + (size_t)r0 * ldA;
    const __half* Bb = Bg + (size_t)b * sB + (size_t)c0 * ldB;

    // per-lane ldmatrix base addresses (byte offsets within a stage)
    //  A x4: matrices [m0-7,k0-7][m8-15,k0-7][m0-7,k8-15][m8-15,k8-15]
    const uint32_t aOff = (uint32_t)(((wm0 + (lane & 15)) * AS + (lane >> 4) * 8) * 2);
    //  B x4: [n0-7,k0-7][n0-7,k8-15][n8-15,k0-7][n8-15,k8-15]
    const uint32_t bOff = TILE_HB +
        (uint32_t)(((wn0 + ((lane >> 4) << 3) + (lane & 7)) * AS + ((lane >> 3) & 1) * 8) * 2);

    float acc[2][8][4];
    #pragma unroll
    for (int mt = 0; mt < 2; ++mt)
        #pragma unroll
        for (int nt = 0; nt < 8; ++nt)
            #pragma unroll
            for (int r = 0; r < 4; ++r) acc[mt][nt][r] = 0.0f;

    auto issue = [&](int c) {
        const int s  = c % NSTAGE;
        const int k0 = c * BK;
        #pragma unroll
        for (int i = 0; i < 4; ++i) {
            const int q   = tid + i * 256;     // 0..1023
            const int isB = q >> 9;
            const int qq  = q & 511;
            const int row = qq >> 2;
            const int seg = qq & 3;            // 16B segment within 64B row
            const char* src = (const char*)((isB ? Bb : Ab)
                            + (size_t)row * (isB ? ldB : ldA) + k0) + seg * 16;
            const uint32_t off = (isB ? TILE_HB : 0u)
                               + (uint32_t)(row * (AS * 2) + seg * 16);
            cp_async16(smemU + s * STAGE_B + off, src);
        }
        asm volatile("cp.async.commit_group;" ::: "memory");
    };

    constexpr int NST = KTOT / BK;
    issue(0); issue(1); issue(2);
    for (int c = 0; c < NST; ++c) {
        if (c + 2 < NST)      asm volatile("cp.async.wait_group 2;" ::: "memory");
        else if (c + 1 < NST) asm volatile("cp.async.wait_group 1;" ::: "memory");
        else                  asm volatile("cp.async.wait_group 0;" ::: "memory");
        __syncthreads();
        if (c + 3 < NST) issue(c + 3);

        const uint32_t stg = smemU + (c % NSTAGE) * STAGE_B;

        #pragma unroll
        for (int ks = 0; ks < 2; ++ks) {
            const uint32_t kb = (uint32_t)(ks * 32);   // 16 halfs = 32 B
            uint32_t af[2][4], bf[8][2];
            #pragma unroll
            for (int mt = 0; mt < 2; ++mt)
                ldsm_x4(af[mt], stg + aOff + mt * (16 * AS * 2) + kb);
            #pragma unroll
            for (int p = 0; p < 4; ++p) {
                uint32_t r[4];
                ldsm_x4(r, stg + bOff + p * (16 * AS * 2) + kb);
                bf[2 * p][0] = r[0]; bf[2 * p][1] = r[1];
                bf[2 * p + 1][0] = r[2]; bf[2 * p + 1][1] = r[3];
            }
            #pragma unroll
            for (int mt = 0; mt < 2; ++mt)
                #pragma unroll
                for (int nt = 0; nt < 8; ++nt)
                    mma_f16(acc[mt][nt], af[mt], bf[nt]);
        }
    }

    // ------------------------------------------------------------------ epi
    float inv2s2 = 0.f;
    if (BIAS) {
        const float s = fabsf(sigma[0]) + 1e-8f;
        inv2s2 = 1.0f / (2.0f * s * s);
    }

    #pragma unroll
    for (int mt = 0; mt < 2; ++mt) {
        #pragma unroll
        for (int h = 0; h < 2; ++h) {
            const int rn = r0 + wm0 + mt * 16 + gq + h * 8;
            float* orow = Og + (size_t)b * sO + (size_t)rn * ldO;
            const float npos = (float)rn * (1.0f / Nc);
            #pragma unroll
            for (int nt = 0; nt < 8; ++nt) {
                const int cn = c0 + wn0 + nt * 8 + 2 * tg;
                float2 v = make_float2(acc[mt][nt][h * 2 + 0],
                                       acc[mt][nt][h * 2 + 1]);
                if (BIAS) {
                    const float d0 = npos - (float)(cn + 0) * (1.0f / Mc);
                    const float d1 = npos - (float)(cn + 1) * (1.0f / Mc);
                    v.x = v.x * 0.03125f - d0 * d0 * inv2s2;
                    v.y = v.y * 0.03125f - d1 * d1 * inv2s2;
                }
                *(float2*)(orow + cn) = v;
            }
        }
    }
}

// ---------------------------------------------------------------------------
// fp32 -> fp16 streaming convert (8 elements/thread)
// ---------------------------------------------------------------------------
__global__ __launch_bounds__(256) void cvt_h(
    const float* __restrict__ in, __half* __restrict__ out)
{
    const size_t i = ((size_t)blockIdx.x * 256 + threadIdx.x) * 8;
    float4 a = *(const float4*)(in + i);
    float4 b = *(const float4*)(in + i + 4);
    __half2 h[4] = {
        __floats2half2_rn(a.x, a.y), __floats2half2_rn(a.z, a.w),
        __floats2half2_rn(b.x, b.y), __floats2half2_rn(b.z, b.w) };
    *(uint4*)(out + i) = *(const uint4*)h;
}

// ---------------------------------------------------------------------------
// audio [b][m][d] fp32 -> g_audioTH [b][d][m] fp16 (32x32 smem tile transpose)
// ---------------------------------------------------------------------------
__global__ __launch_bounds__(256) void transpose_h(const float* __restrict__ audio)
{
    __shared__ __half t[32][33];
    const int b  = blockIdx.z;
    const int m0 = blockIdx.x * 32;
    const int d0 = blockIdx.y * 32;
    const int tx = threadIdx.x & 31;
    const int ty = threadIdx.x >> 5;    // 0..7

    const float* src = audio + (size_t)b * Mc * Dc;
    #pragma unroll
    for (int i = 0; i < 4; ++i)
        t[ty + i * 8][tx] = __float2half_rn(src[(size_t)(m0 + ty + i * 8) * Dc + d0 + tx]);
    __syncthreads();
    __half* dst = g_audioTH + (size_t)b * Dc * Mc;
    #pragma unroll
    for (int i = 0; i < 4; ++i)
        dst[(size_t)(d0 + ty + i * 8) * Mc + m0 + tx] = t[tx][ty + i * 8];
}

// ---------------------------------------------------------------------------
// Masked row softmax over M=2048; one block of 256 per (b,n) row.
// Stores: fp32 (unrounded) in place (d_out) + fp16 copy for GEMM2.
// ---------------------------------------------------------------------------
__global__ __launch_bounds__(256) void softmax_rows(
    float* __restrict__ attn, const int* __restrict__ lens)
{
    const int row = blockIdx.x;
    const int b = row >> 10;
    const int len = lens[b];
    float*  P  = attn    + (size_t)row * Mc;
    __half* PH = g_attnH + (size_t)row * Mc;
    const int tid  = threadIdx.x;
    const int lane = tid & 31;
    const int wrp  = tid >> 5;
    const int j0   = tid * 8;

    __shared__ float red[8];

    float4 v0 = *(const float4*)(P + j0);
    float4 v1 = *(const float4*)(P + j0 + 4);
    float vals[8] = {
        (j0 + 0 < len) ? v0.x : -INFINITY, (j0 + 1 < len) ? v0.y : -INFINITY,
        (j0 + 2 < len) ? v0.z : -INFINITY, (j0 + 3 < len) ? v0.w : -INFINITY,
        (j0 + 4 < len) ? v1.x : -INFINITY, (j0 + 5 < len) ? v1.y : -INFINITY,
        (j0 + 6 < len) ? v1.z : -INFINITY, (j0 + 7 < len) ? v1.w : -INFINITY };

    float mx = vals[0];
    #pragma unroll
    for (int t = 1; t < 8; ++t) mx = fmaxf(mx, vals[t]);
    #pragma unroll
    for (int o = 16; o > 0; o >>= 1) mx = fmaxf(mx, __shfl_xor_sync(~0u, mx, o));
    if (lane == 0) red[wrp] = mx;
    __syncthreads();
    {
        float t = red[lane & 7];
        #pragma unroll
        for (int o = 4; o > 0; o >>= 1) t = fmaxf(t, __shfl_xor_sync(~0u, t, o));
        mx = t;
    }

    float sum = 0.0f;
    #pragma unroll
    for (int t = 0; t < 8; ++t) {
        const float e = (vals[t] == -INFINITY) ? 0.0f : __expf(vals[t] - mx);
        vals[t] = e;
        sum += e;
    }
    #pragma unroll
    for (int o = 16; o > 0; o >>= 1) sum += __shfl_xor_sync(~0u, sum, o);
    __syncthreads();
    if (lane == 0) red[wrp] = sum;
    __syncthreads();
    {
        float t = red[lane & 7];
        #pragma unroll
        for (int o = 4; o > 0; o >>= 1) t += __shfl_xor_sync(~0u, t, o);
        sum = t;
    }
    const float inv = 1.0f / sum;

    float w[8];
    #pragma unroll
    for (int t = 0; t < 8; ++t) w[t] = vals[t] * inv;

    *(float4*)(P + j0)     = make_float4(w[0], w[1], w[2], w[3]);
    *(float4*)(P + j0 + 4) = make_float4(w[4], w[5], w[6], w[7]);

    __half2 h[4] = {
        __floats2half2_rn(w[0], w[1]), __floats2half2_rn(w[2], w[3]),
        __floats2half2_rn(w[4], w[5]), __floats2half2_rn(w[6], w[7]) };
    *(uint4*)(PH + j0) = *(const uint4*)h;
}

// ---------------------------------------------------------------------------
extern "C" void kernel_launch(void* const* d_in, const int* in_sizes, int n_in,
                              void* d_out, int out_size)
{
    const float* text  = (const float*)d_in[0];
    const float* audio = (const float*)d_in[1];
    const float* sigma = (const float*)d_in[2];
    const int*   lens  = (const int*)d_in[3];

    float* enhanced = (float*)d_out;                    // B*N*D
    float* attn     = enhanced + (size_t)Bc * Nc * Dc;  // B*N*M (scores scratch)

    void *textH_p = nullptr, *audioH_p = nullptr, *audioTH_p = nullptr, *attnH_p = nullptr;
    cudaGetSymbolAddress(&textH_p,   g_textH);
    cudaGetSymbolAddress(&audioH_p,  g_audioH);
    cudaGetSymbolAddress(&audioTH_p, g_audioTH);
    cudaGetSymbolAddress(&attnH_p,   g_attnH);

    cudaFuncSetAttribute(tc_gemm<Dc, true>,
                         cudaFuncAttributeMaxDynamicSharedMemorySize, SMEM_B);
    cudaFuncSetAttribute(tc_gemm<Mc, false>,
                         cudaFuncAttributeMaxDynamicSharedMemorySize, SMEM_B);

    cvt_h<<<(Bc * Nc * Dc) / 2048, 256>>>(text,  (__half*)textH_p);
    cvt_h<<<(Bc * Mc * Dc) / 2048, 256>>>(audio, (__half*)audioH_p);
    transpose_h<<<dim3(Mc / 32, Dc / 32, Bc), 256>>>(audio);

    // GEMM1: scores = textH . audioH^T (+bias) -> attn
    tc_gemm<Dc, true><<<dim3(Mc / 128, Nc / 128, Bc), 256, SMEM_B>>>(
        (const __half*)textH_p, (const __half*)audioH_p, attn,
        (size_t)Nc * Dc, (size_t)Mc * Dc, (size_t)Nc * Mc,
        Dc, Dc, Mc, sigma);

    softmax_rows<<<Bc * Nc, 256>>>(attn, lens);

    // GEMM2: enhanced = attnH . audioTH^T  (K-major over m on both sides)
    tc_gemm<Mc, false><<<dim3(Dc / 128, Nc / 128, Bc), 256, SMEM_B>>>(
        (const __half*)attnH_p, (const __half*)audioTH_p, enhanced,
        (size_t)Nc * Mc, (size_t)Dc * Mc, (size_t)Nc * Dc,
        Mc, Mc, Dc, nullptr);
}

// round 13
// speedup vs baseline: 1.7177x; 1.0203x over previous
#include <cuda_runtime.h>
#include <cuda_fp16.h>
#include <math.h>
#include <stdint.h>

#define Bc 8
#define Nc 1024
#define Mc 2048
#define Dc 1024

// fp16 scratch (allocation-free rule), all K-major for their GEMM use
__device__ __half g_textH  [(size_t)Bc * Nc * Dc];   // [b][n][d]
__device__ __half g_audioH [(size_t)Bc * Mc * Dc];   // [b][m][d]
__device__ __half g_audioTH[(size_t)Bc * Dc * Mc];   // [b][d][m]
__device__ __half g_attnH  [(size_t)Bc * Nc * Mc];   // [b][n][m]

__device__ __forceinline__ void cp_async16(uint32_t dst, const void* src) {
    asm volatile("cp.async.cg.shared.global [%0], [%1], 16;" :: "r"(dst), "l"(src) : "memory");
}
__device__ __forceinline__ void mma_f16(float* c, const uint32_t* a, const uint32_t* b) {
    asm volatile(
        "mma.sync.aligned.m16n8k16.row.col.f32.f16.f16.f32 "
        "{%0,%1,%2,%3}, {%4,%5,%6,%7}, {%8,%9}, {%0,%1,%2,%3};"
        : "+f"(c[0]), "+f"(c[1]), "+f"(c[2]), "+f"(c[3])
        : "r"(a[0]), "r"(a[1]), "r"(a[2]), "r"(a[3]), "r"(b[0]), "r"(b[1]));
}
__device__ __forceinline__ void ldsm_x4(uint32_t* r, uint32_t addr) {
    asm volatile("ldmatrix.sync.aligned.m8n8.x4.shared.b16 {%0,%1,%2,%3}, [%4];"
        : "=r"(r[0]), "=r"(r[1]), "=r"(r[2]), "=r"(r[3]) : "r"(addr));
}

#define BM 128         // CTA rows (out rows)
#define BN 64          // CTA cols (out cols)
#define BK 32          // K chunk per stage (halfs)
#define AS 40          // smem row stride in halfs (80 B): LDSM conflict-free
#define A_HB (BM * AS * 2)              // 10240 B
#define B_HB (BN * AS * 2)              // 5120 B
#define STAGE_B (A_HB + B_HB)           // 15360 B per stage
#define NSTAGE  3
#define SMEM_B  (NSTAGE * STAGE_B)      // 46080 B  -> 4 CTAs/SM

// ---------------------------------------------------------------------------
// fp16 tensor-core GEMM: D[128x64] = A[128xK] . B[64xK]^T per CTA tile.
// 4 warps (32x64 warp tile), m16n8k16, ldmatrix, 3-stage cp.async pipeline.
// 4 CTAs/SM -> decoupled barriers. BIAS fuses /sqrt(D)+Gaussian bias (GEMM1).
// ---------------------------------------------------------------------------
template<int KTOT, bool BIAS>
__global__ __launch_bounds__(128, 4) void tc_gemm(
    const __half* __restrict__ Ag, const __half* __restrict__ Bg,
    float* __restrict__ Og,
    size_t sA, size_t sB, size_t sO,
    int ldA, int ldB, int ldO,
    const float* __restrict__ sigma)
{
    extern __shared__ char smc[];
    const uint32_t smemU = (uint32_t)__cvta_generic_to_shared(smc);
    const int tid  = threadIdx.x;
    const int lane = tid & 31;
    const int wid  = tid >> 5;          // 0..3
    const int wm0  = wid * 32;          // warp row offset
    const int gq   = lane >> 2;
    const int tg   = lane & 3;

    const int b  = blockIdx.z;
    const int r0 = blockIdx.y * BM;
    const int c0 = blockIdx.x * BN;

    const __half* Ab = Ag + (size_t)b * sA + (size_t)r0 * ldA;
    const __half* Bb = Bg + (size_t)b * sB + (size_t)c0 * ldB;

    // ldmatrix per-lane base byte offsets within a stage
    const uint32_t aOff = (uint32_t)(((wm0 + (lane & 15)) * AS + (lane >> 4) * 8) * 2);
    const uint32_t bOff = A_HB +
        (uint32_t)(((((lane >> 4) << 3) + (lane & 7)) * AS + ((lane >> 3) & 1) * 8) * 2);

    float acc[2][8][4];
    #pragma unroll
    for (int mt = 0; mt < 2; ++mt)
        #pragma unroll
        for (int nt = 0; nt < 8; ++nt)
            #pragma unroll
            for (int r = 0; r < 4; ++r) acc[mt][nt][r] = 0.0f;

    auto issue = [&](int c) {
        const int s  = c % NSTAGE;
        const int k0 = c * BK;
        #pragma unroll
        for (int i = 0; i < 6; ++i) {
            const int q   = tid + i * 128;     // 0..767
            const int isB = q >> 9;            // >=512 -> B
            const int qq  = isB ? (q - 512) : q;
            const int row = qq >> 2;
            const int seg = qq & 3;            // 16B segment within 64B of K
            const char* src = (const char*)((isB ? Bb : Ab)
                            + (size_t)row * (isB ? ldB : ldA) + k0) + seg * 16;
            const uint32_t off = (isB ? A_HB : 0u)
                               + (uint32_t)(row * (AS * 2) + seg * 16);
            cp_async16(smemU + s * STAGE_B + off, src);
        }
        asm volatile("cp.async.commit_group;" ::: "memory");
    };

    constexpr int NST = KTOT / BK;
    issue(0);
    issue(1);
    for (int c = 0; c < NST; ++c) {
        if (c + 1 < NST) asm volatile("cp.async.wait_group 1;" ::: "memory");
        else             asm volatile("cp.async.wait_group 0;" ::: "memory");
        __syncthreads();
        if (c + 2 < NST) issue(c + 2);

        const uint32_t stg = smemU + (c % NSTAGE) * STAGE_B;

        #pragma unroll
        for (int ks = 0; ks < 2; ++ks) {
            const uint32_t kb = (uint32_t)(ks * 32);   // 16 halfs = 32 B
            uint32_t af[2][4], bf[8][2];
            #pragma unroll
            for (int mt = 0; mt < 2; ++mt)
                ldsm_x4(af[mt], stg + aOff + mt * (16 * AS * 2) + kb);
            #pragma unroll
            for (int p = 0; p < 4; ++p) {
                uint32_t r[4];
                ldsm_x4(r, stg + bOff + p * (16 * AS * 2) + kb);
                bf[2 * p][0] = r[0];     bf[2 * p][1] = r[1];
                bf[2 * p + 1][0] = r[2]; bf[2 * p + 1][1] = r[3];
            }
            #pragma unroll
            for (int mt = 0; mt < 2; ++mt)
                #pragma unroll
                for (int nt = 0; nt < 8; ++nt)
                    mma_f16(acc[mt][nt], af[mt], bf[nt]);
        }
    }

    // ------------------------------------------------------------------ epi
    float inv2s2 = 0.f;
    if (BIAS) {
        const float s = fabsf(sigma[0]) + 1e-8f;
        inv2s2 = 1.0f / (2.0f * s * s);
    }

    #pragma unroll
    for (int mt = 0; mt < 2; ++mt) {
        #pragma unroll
        for (int h = 0; h < 2; ++h) {
            const int rn = r0 + wm0 + mt * 16 + gq + h * 8;
            float* orow = Og + (size_t)b * sO + (size_t)rn * ldO;
            const float npos = (float)rn * (1.0f / Nc);
            #pragma unroll
            for (int nt = 0; nt < 8; ++nt) {
                const int cn = c0 + nt * 8 + 2 * tg;
                float2 v = make_float2(acc[mt][nt][h * 2 + 0],
                                       acc[mt][nt][h * 2 + 1]);
                if (BIAS) {
                    const float d0 = npos - (float)(cn + 0) * (1.0f / Mc);
                    const float d1 = npos - (float)(cn + 1) * (1.0f / Mc);
                    v.x = v.x * 0.03125f - d0 * d0 * inv2s2;
                    v.y = v.y * 0.03125f - d1 * d1 * inv2s2;
                }
                *(float2*)(orow + cn) = v;
            }
        }
    }
}

// ---------------------------------------------------------------------------
// fp32 -> fp16 streaming convert (8 elements/thread)
// ---------------------------------------------------------------------------
__global__ __launch_bounds__(256) void cvt_h(
    const float* __restrict__ in, __half* __restrict__ out)
{
    const size_t i = ((size_t)blockIdx.x * 256 + threadIdx.x) * 8;
    float4 a = *(const float4*)(in + i);
    float4 b = *(const float4*)(in + i + 4);
    __half2 h[4] = {
        __floats2half2_rn(a.x, a.y), __floats2half2_rn(a.z, a.w),
        __floats2half2_rn(b.x, b.y), __floats2half2_rn(b.z, b.w) };
    *(uint4*)(out + i) = *(const uint4*)h;
}

// ---------------------------------------------------------------------------
// audio [b][m][d] fp32 -> g_audioTH [b][d][m] fp16 (32x32 smem tile transpose)
// ---------------------------------------------------------------------------
__global__ __launch_bounds__(256) void transpose_h(const float* __restrict__ audio)
{
    __shared__ __half t[32][33];
    const int b  = blockIdx.z;
    const int m0 = blockIdx.x * 32;
    const int d0 = blockIdx.y * 32;
    const int tx = threadIdx.x & 31;
    const int ty = threadIdx.x >> 5;    // 0..7

    const float* src = audio + (size_t)b * Mc * Dc;
    #pragma unroll
    for (int i = 0; i < 4; ++i)
        t[ty + i * 8][tx] = __float2half_rn(src[(size_t)(m0 + ty + i * 8) * Dc + d0 + tx]);
    __syncthreads();
    __half* dst = g_audioTH + (size_t)b * Dc * Mc;
    #pragma unroll
    for (int i = 0; i < 4; ++i)
        dst[(size_t)(d0 + ty + i * 8) * Mc + m0 + tx] = t[tx][ty + i * 8];
}

// ---------------------------------------------------------------------------
// Masked row softmax over M=2048; one block of 256 per (b,n) row.
// Stores: fp32 (unrounded) in place (d_out) + fp16 copy for GEMM2.
// ---------------------------------------------------------------------------
__global__ __launch_bounds__(256) void softmax_rows(
    float* __restrict__ attn, const int* __restrict__ lens)
{
    const int row = blockIdx.x;
    const int b = row >> 10;
    const int len = lens[b];
    float*  P  = attn    + (size_t)row * Mc;
    __half* PH = g_attnH + (size_t)row * Mc;
    const int tid  = threadIdx.x;
    const int lane = tid & 31;
    const int wrp  = tid >> 5;
    const int j0   = tid * 8;

    __shared__ float red[8];

    float4 v0 = *(const float4*)(P + j0);
    float4 v1 = *(const float4*)(P + j0 + 4);
    float vals[8] = {
        (j0 + 0 < len) ? v0.x : -INFINITY, (j0 + 1 < len) ? v0.y : -INFINITY,
        (j0 + 2 < len) ? v0.z : -INFINITY, (j0 + 3 < len) ? v0.w : -INFINITY,
        (j0 + 4 < len) ? v1.x : -INFINITY, (j0 + 5 < len) ? v1.y : -INFINITY,
        (j0 + 6 < len) ? v1.z : -INFINITY, (j0 + 7 < len) ? v1.w : -INFINITY };

    float mx = vals[0];
    #pragma unroll
    for (int t = 1; t < 8; ++t) mx = fmaxf(mx, vals[t]);
    #pragma unroll
    for (int o = 16; o > 0; o >>= 1) mx = fmaxf(mx, __shfl_xor_sync(~0u, mx, o));
    if (lane == 0) red[wrp] = mx;
    __syncthreads();
    {
        float t = red[lane & 7];
        #pragma unroll
        for (int o = 4; o > 0; o >>= 1) t = fmaxf(t, __shfl_xor_sync(~0u, t, o));
        mx = t;
    }

    float sum = 0.0f;
    #pragma unroll
    for (int t = 0; t < 8; ++t) {
        const float e = (vals[t] == -INFINITY) ? 0.0f : __expf(vals[t] - mx);
        vals[t] = e;
        sum += e;
    }
    #pragma unroll
    for (int o = 16; o > 0; o >>= 1) sum += __shfl_xor_sync(~0u, sum, o);
    __syncthreads();
    if (lane == 0) red[wrp] = sum;
    __syncthreads();
    {
        float t = red[lane & 7];
        #pragma unroll
        for (int o = 4; o > 0; o >>= 1) t += __shfl_xor_sync(~0u, t, o);
        sum = t;
    }
    const float inv = 1.0f / sum;

    float w[8];
    #pragma unroll
    for (int t = 0; t < 8; ++t) w[t] = vals[t] * inv;

    *(float4*)(P + j0)     = make_float4(w[0], w[1], w[2], w[3]);
    *(float4*)(P + j0 + 4) = make_float4(w[4], w[5], w[6], w[7]);

    __half2 h[4] = {
        __floats2half2_rn(w[0], w[1]), __floats2half2_rn(w[2], w[3]),
        __floats2half2_rn(w[4], w[5]), __floats2half2_rn(w[6], w[7]) };
    *(uint4*)(PH + j0) = *(const uint4*)h;
}

// ---------------------------------------------------------------------------
extern "C" void kernel_launch(void* const* d_in, const int* in_sizes, int n_in,
                              void* d_out, int out_size)
{
    const float* text  = (const float*)d_in[0];
    const float* audio = (const float*)d_in[1];
    const float* sigma = (const float*)d_in[2];
    const int*   lens  = (const int*)d_in[3];

    float* enhanced = (float*)d_out;                    // B*N*D
    float* attn     = enhanced + (size_t)Bc * Nc * Dc;  // B*N*M (scores scratch)

    void *textH_p = nullptr, *audioH_p = nullptr, *audioTH_p = nullptr, *attnH_p = nullptr;
    cudaGetSymbolAddress(&textH_p,   g_textH);
    cudaGetSymbolAddress(&audioH_p,  g_audioH);
    cudaGetSymbolAddress(&audioTH_p, g_audioTH);
    cudaGetSymbolAddress(&attnH_p,   g_attnH);

    cudaFuncSetAttribute(tc_gemm<Dc, true>,
                         cudaFuncAttributeMaxDynamicSharedMemorySize, SMEM_B);
    cudaFuncSetAttribute(tc_gemm<Mc, false>,
                         cudaFuncAttributeMaxDynamicSharedMemorySize, SMEM_B);

    cvt_h<<<(Bc * Nc * Dc) / 2048, 256>>>(text,  (__half*)textH_p);
    cvt_h<<<(Bc * Mc * Dc) / 2048, 256>>>(audio, (__half*)audioH_p);
    transpose_h<<<dim3(Mc / 32, Dc / 32, Bc), 256>>>(audio);

    // GEMM1: scores = textH . audioH^T (+bias) -> attn
    tc_gemm<Dc, true><<<dim3(Mc / BN, Nc / BM, Bc), 128, SMEM_B>>>(
        (const __half*)textH_p, (const __half*)audioH_p, attn,
        (size_t)Nc * Dc, (size_t)Mc * Dc, (size_t)Nc * Mc,
        Dc, Dc, Mc, sigma);

    softmax_rows<<<Bc * Nc, 256>>>(attn, lens);

    // GEMM2: enhanced = attnH . audioTH^T  (K-major over m on both sides)
    tc_gemm<Mc, false><<<dim3(Dc / BN, Nc / BM, Bc), 128, SMEM_B>>>(
        (const __half*)attnH_p, (const __half*)audioTH_p, enhanced,
        (size_t)Nc * Mc, (size_t)Dc * Mc, (size_t)Nc * Dc,
        Mc, Mc, Dc, nullptr);
}

// round 15
// speedup vs baseline: 2.5526x; 1.4861x over previous
#include <cuda_runtime.h>
#include <cuda_fp16.h>
#include <math.h>
#include <stdint.h>

#define Bc 8
#define Nc 1024
#define Mc 2048
#define Dc 1024

// fp16 scratch (allocation-free rule), all K-major for their GEMM use
__device__ __half g_textH  [(size_t)Bc * Nc * Dc];   // [b][n][d]
__device__ __half g_audioH [(size_t)Bc * Mc * Dc];   // [b][m][d]
__device__ __half g_audioTH[(size_t)Bc * Dc * Mc];   // [b][d][m]
__device__ __half g_attnH  [(size_t)Bc * Nc * Mc];   // [b][n][m]

__device__ __forceinline__ void cp_async16(uint32_t dst, const void* src) {
    asm volatile("cp.async.cg.shared.global [%0], [%1], 16;" :: "r"(dst), "l"(src) : "memory");
}
__device__ __forceinline__ void mma_f16(float* c, const uint32_t* a, const uint32_t* b) {
    asm volatile(
        "mma.sync.aligned.m16n8k16.row.col.f32.f16.f16.f32 "
        "{%0,%1,%2,%3}, {%4,%5,%6,%7}, {%8,%9}, {%0,%1,%2,%3};"
        : "+f"(c[0]), "+f"(c[1]), "+f"(c[2]), "+f"(c[3])
        : "r"(a[0]), "r"(a[1]), "r"(a[2]), "r"(a[3]), "r"(b[0]), "r"(b[1]));
}
__device__ __forceinline__ void ldsm_x4(uint32_t* r, uint32_t addr) {
    asm volatile("ldmatrix.sync.aligned.m8n8.x4.shared.b16 {%0,%1,%2,%3}, [%4];"
        : "=r"(r[0]), "=r"(r[1]), "=r"(r[2]), "=r"(r[3]) : "r"(addr));
}

#define BM 128         // CTA rows (out rows)
#define BN 64          // CTA cols (out cols)
#define BK 32          // K chunk per stage (halfs)
#define AS 40          // smem row stride in halfs (80 B): LDSM conflict-free
#define A_HB (BM * AS * 2)              // 10240 B
#define B_HB (BN * AS * 2)              // 5120 B
#define STAGE_B (A_HB + B_HB)           // 15360 B per stage
#define NSTAGE  3
#define SMEM_B  (NSTAGE * STAGE_B)      // 46080 B  -> 4 CTAs/SM

// ---------------------------------------------------------------------------
// fp16 tensor-core GEMM: D[128x64] = A[128xK] . B[64xK]^T per CTA tile.
// 4 warps (32x64 warp tile), m16n8k16, ldmatrix, 3-stage cp.async pipeline.
//  BIAS : GEMM1 — fuse /sqrt(D)+Gaussian bias; early-exit m-tiles >= len.
//  KDYN : GEMM2 — runtime K bound = round_up(len, BK) (attnH is 0 beyond len).
// ---------------------------------------------------------------------------
template<int KTOT, bool BIAS, bool KDYN>
__global__ __launch_bounds__(128, 4) void tc_gemm(
    const __half* __restrict__ Ag, const __half* __restrict__ Bg,
    float* __restrict__ Og,
    size_t sA, size_t sB, size_t sO,
    int ldA, int ldB, int ldO,
    const float* __restrict__ sigma,
    const int* __restrict__ lens)
{
    const int b  = blockIdx.z;
    const int r0 = blockIdx.y * BM;
    const int c0 = blockIdx.x * BN;

    const int len = lens[b];
    if (BIAS && c0 >= len) return;   // masked m-tile: softmax writes 0 anyway

    constexpr int NSTC = KTOT / BK;
    const int nst = KDYN ? ((len + BK - 1) >> 5) : NSTC;   // >= 16 (len >= 512)

    extern __shared__ char smc[];
    const uint32_t smemU = (uint32_t)__cvta_generic_to_shared(smc);
    const int tid  = threadIdx.x;
    const int lane = tid & 31;
    const int wid  = tid >> 5;          // 0..3
    const int wm0  = wid * 32;          // warp row offset
    const int gq   = lane >> 2;
    const int tg   = lane & 3;

    const __half* Ab = Ag + (size_t)b * sA + (size_t)r0 * ldA;
    const __half* Bb = Bg + (size_t)b * sB + (size_t)c0 * ldB;

    // ldmatrix per-lane base byte offsets within a stage
    const uint32_t aOff = (uint32_t)(((wm0 + (lane & 15)) * AS + (lane >> 4) * 8) * 2);
    const uint32_t bOff = A_HB +
        (uint32_t)(((((lane >> 4) << 3) + (lane & 7)) * AS + ((lane >> 3) & 1) * 8) * 2);

    float acc[2][8][4];
    #pragma unroll
    for (int mt = 0; mt < 2; ++mt)
        #pragma unroll
        for (int nt = 0; nt < 8; ++nt)
            #pragma unroll
            for (int r = 0; r < 4; ++r) acc[mt][nt][r] = 0.0f;

    auto issue = [&](int c) {
        const int s  = c % NSTAGE;
        const int k0 = c * BK;
        #pragma unroll
        for (int i = 0; i < 6; ++i) {
            const int q   = tid + i * 128;     // 0..767
            const int isB = q >> 9;            // >=512 -> B
            const int qq  = isB ? (q - 512) : q;
            const int row = qq >> 2;
            const int seg = qq & 3;            // 16B segment within 64B of K
            const char* src = (const char*)((isB ? Bb : Ab)
                            + (size_t)row * (isB ? ldB : ldA) + k0) + seg * 16;
            const uint32_t off = (isB ? A_HB : 0u)
                               + (uint32_t)(row * (AS * 2) + seg * 16);
            cp_async16(smemU + s * STAGE_B + off, src);
        }
        asm volatile("cp.async.commit_group;" ::: "memory");
    };

    issue(0);
    issue(1);
    for (int c = 0; c < nst; ++c) {
        if (c + 1 < nst) asm volatile("cp.async.wait_group 1;" ::: "memory");
        else             asm volatile("cp.async.wait_group 0;" ::: "memory");
        __syncthreads();
        if (c + 2 < nst) issue(c + 2);

        const uint32_t stg = smemU + (c % NSTAGE) * STAGE_B;

        #pragma unroll
        for (int ks = 0; ks < 2; ++ks) {
            const uint32_t kb = (uint32_t)(ks * 32);   // 16 halfs = 32 B
            uint32_t af[2][4], bf[8][2];
            #pragma unroll
            for (int mt = 0; mt < 2; ++mt)
                ldsm_x4(af[mt], stg + aOff + mt * (16 * AS * 2) + kb);
            #pragma unroll
            for (int p = 0; p < 4; ++p) {
                uint32_t r[4];
                ldsm_x4(r, stg + bOff + p * (16 * AS * 2) + kb);
                bf[2 * p][0] = r[0];     bf[2 * p][1] = r[1];
                bf[2 * p + 1][0] = r[2]; bf[2 * p + 1][1] = r[3];
            }
            #pragma unroll
            for (int mt = 0; mt < 2; ++mt)
                #pragma unroll
                for (int nt = 0; nt < 8; ++nt)
                    mma_f16(acc[mt][nt], af[mt], bf[nt]);
        }
    }

    // ------------------------------------------------------------------ epi
    float inv2s2 = 0.f;
    if (BIAS) {
        const float s = fabsf(sigma[0]) + 1e-8f;
        inv2s2 = 1.0f / (2.0f * s * s);
    }

    #pragma unroll
    for (int mt = 0; mt < 2; ++mt) {
        #pragma unroll
        for (int h = 0; h < 2; ++h) {
            const int rn = r0 + wm0 + mt * 16 + gq + h * 8;
            float* orow = Og + (size_t)b * sO + (size_t)rn * ldO;
            const float npos = (float)rn * (1.0f / Nc);
            #pragma unroll
            for (int nt = 0; nt < 8; ++nt) {
                const int cn = c0 + nt * 8 + 2 * tg;
                float2 v = make_float2(acc[mt][nt][h * 2 + 0],
                                       acc[mt][nt][h * 2 + 1]);
                if (BIAS) {
                    const float d0 = npos - (float)(cn + 0) * (1.0f / Mc);
                    const float d1 = npos - (float)(cn + 1) * (1.0f / Mc);
                    v.x = v.x * 0.03125f - d0 * d0 * inv2s2;
                    v.y = v.y * 0.03125f - d1 * d1 * inv2s2;
                }
                *(float2*)(orow + cn) = v;
            }
        }
    }
}

// ---------------------------------------------------------------------------
// fp32 -> fp16 streaming convert (8 elements/thread)  [text]
// ---------------------------------------------------------------------------
__global__ __launch_bounds__(256) void cvt_h(
    const float* __restrict__ in, __half* __restrict__ out)
{
    const size_t i = ((size_t)blockIdx.x * 256 + threadIdx.x) * 8;
    float4 a = *(const float4*)(in + i);
    float4 b = *(const float4*)(in + i + 4);
    __half2 h[4] = {
        __floats2half2_rn(a.x, a.y), __floats2half2_rn(a.z, a.w),
        __floats2half2_rn(b.x, b.y), __floats2half2_rn(b.z, b.w) };
    *(uint4*)(out + i) = *(const uint4*)h;
}

// ---------------------------------------------------------------------------
// audio fp32 [b][m][d] -> g_audioH (same layout) + g_audioTH (transposed),
// single read of the fp32 source.
// ---------------------------------------------------------------------------
__global__ __launch_bounds__(256) void prep_audio(const float* __restrict__ audio)
{
    __shared__ __half t[32][33];
    const int b  = blockIdx.z;
    const int m0 = blockIdx.x * 32;
    const int d0 = blockIdx.y * 32;
    const int tx = threadIdx.x & 31;
    const int ty = threadIdx.x >> 5;    // 0..7

    const float* src = audio + (size_t)b * Mc * Dc;
    __half* dstH = g_audioH + (size_t)b * Mc * Dc;
    #pragma unroll
    for (int i = 0; i < 4; ++i) {
        const int m = m0 + ty + i * 8;
        const __half h = __float2half_rn(src[(size_t)m * Dc + d0 + tx]);
        t[ty + i * 8][tx] = h;
        dstH[(size_t)m * Dc + d0 + tx] = h;
    }
    __syncthreads();
    __half* dstT = g_audioTH + (size_t)b * Dc * Mc;
    #pragma unroll
    for (int i = 0; i < 4; ++i)
        dstT[(size_t)(d0 + ty + i * 8) * Mc + m0 + tx] = t[tx][ty + i * 8];
}

// ---------------------------------------------------------------------------
// Masked row softmax over M=2048; one block of 256 per (b,n) row.
// Stores: fp32 (unrounded) in place (d_out) + fp16 copy for GEMM2.
// Writes the FULL row (0 for masked cols) — GEMM1's skipped tiles rely on it.
// ---------------------------------------------------------------------------
__global__ __launch_bounds__(256) void softmax_rows(
    float* __restrict__ attn, const int* __restrict__ lens)
{
    const int row = blockIdx.x;
    const int b = row >> 10;
    const int len = lens[b];
    float*  P  = attn    + (size_t)row * Mc;
    __half* PH = g_attnH + (size_t)row * Mc;
    const int tid  = threadIdx.x;
    const int lane = tid & 31;
    const int wrp  = tid >> 5;
    const int j0   = tid * 8;

    __shared__ float red[8];

    float4 v0 = *(const float4*)(P + j0);
    float4 v1 = *(const float4*)(P + j0 + 4);
    float vals[8] = {
        (j0 + 0 < len) ? v0.x : -INFINITY, (j0 + 1 < len) ? v0.y : -INFINITY,
        (j0 + 2 < len) ? v0.z : -INFINITY, (j0 + 3 < len) ? v0.w : -INFINITY,
        (j0 + 4 < len) ? v1.x : -INFINITY, (j0 + 5 < len) ? v1.y : -INFINITY,
        (j0 + 6 < len) ? v1.z : -INFINITY, (j0 + 7 < len) ? v1.w : -INFINITY };

    float mx = vals[0];
    #pragma unroll
    for (int t = 1; t < 8; ++t) mx = fmaxf(mx, vals[t]);
    #pragma unroll
    for (int o = 16; o > 0; o >>= 1) mx = fmaxf(mx, __shfl_xor_sync(~0u, mx, o));
    if (lane == 0) red[wrp] = mx;
    __syncthreads();
    {
        float t = red[lane & 7];
        #pragma unroll
        for (int o = 4; o > 0; o >>= 1) t = fmaxf(t, __shfl_xor_sync(~0u, t, o));
        mx = t;
    }

    float sum = 0.0f;
    #pragma unroll
    for (int t = 0; t < 8; ++t) {
        const float e = (vals[t] == -INFINITY) ? 0.0f : __expf(vals[t] - mx);
        vals[t] = e;
        sum += e;
    }
    #pragma unroll
    for (int o = 16; o > 0; o >>= 1) sum += __shfl_xor_sync(~0u, sum, o);
    __syncthreads();
    if (lane == 0) red[wrp] = sum;
    __syncthreads();
    {
        float t = red[lane & 7];
        #pragma unroll
        for (int o = 4; o > 0; o >>= 1) t += __shfl_xor_sync(~0u, t, o);
        sum = t;
    }
    const float inv = 1.0f / sum;

    float w[8];
    #pragma unroll
    for (int t = 0; t < 8; ++t) w[t] = vals[t] * inv;

    *(float4*)(P + j0)     = make_float4(w[0], w[1], w[2], w[3]);
    *(float4*)(P + j0 + 4) = make_float4(w[4], w[5], w[6], w[7]);

    __half2 h[4] = {
        __floats2half2_rn(w[0], w[1]), __floats2half2_rn(w[2], w[3]),
        __floats2half2_rn(w[4], w[5]), __floats2half2_rn(w[6], w[7]) };
    *(uint4*)(PH + j0) = *(const uint4*)h;
}

// ---------------------------------------------------------------------------
extern "C" void kernel_launch(void* const* d_in, const int* in_sizes, int n_in,
                              void* d_out, int out_size)
{
    const float* text  = (const float*)d_in[0];
    const float* audio = (const float*)d_in[1];
    const float* sigma = (const float*)d_in[2];
    const int*   lens  = (const int*)d_in[3];

    float* enhanced = (float*)d_out;                    // B*N*D
    float* attn     = enhanced + (size_t)Bc * Nc * Dc;  // B*N*M (scores scratch)

    void *textH_p = nullptr, *audioH_p = nullptr, *audioTH_p = nullptr, *attnH_p = nullptr;
    cudaGetSymbolAddress(&textH_p,   g_textH);
    cudaGetSymbolAddress(&audioH_p,  g_audioH);
    cudaGetSymbolAddress(&audioTH_p, g_audioTH);
    cudaGetSymbolAddress(&attnH_p,   g_attnH);

    cudaFuncSetAttribute(tc_gemm<Dc, true, false>,
                         cudaFuncAttributeMaxDynamicSharedMemorySize, SMEM_B);
    cudaFuncSetAttribute(tc_gemm<Mc, false, true>,
                         cudaFuncAttributeMaxDynamicSharedMemorySize, SMEM_B);

    cvt_h<<<(Bc * Nc * Dc) / 2048, 256>>>(text, (__half*)textH_p);
    prep_audio<<<dim3(Mc / 32, Dc / 32, Bc), 256>>>(audio);

    // GEMM1: scores = textH . audioH^T (+bias) -> attn; skips m-tiles >= len
    tc_gemm<Dc, true, false><<<dim3(Mc / BN, Nc / BM, Bc), 128, SMEM_B>>>(
        (const __half*)textH_p, (const __half*)audioH_p, attn,
        (size_t)Nc * Dc, (size_t)Mc * Dc, (size_t)Nc * Mc,
        Dc, Dc, Mc, sigma, lens);

    softmax_rows<<<Bc * Nc, 256>>>(attn, lens);

    // GEMM2: enhanced = attnH . audioTH^T; K bounded by round_up(len, 32)
    tc_gemm<Mc, false, true><<<dim3(Dc / BN, Nc / BM, Bc), 128, SMEM_B>>>(
        (const __half*)attnH_p, (const __half*)audioTH_p, enhanced,
        (size_t)Nc * Mc, (size_t)Dc * Mc, (size_t)Nc * Dc,
        Mc, Mc, Dc, nullptr, lens);
}

// round 16
// speedup vs baseline: 2.7720x; 1.0859x over previous
#include <cuda_runtime.h>
#include <cuda_fp16.h>
#include <math.h>
#include <stdint.h>

#define Bc 8
#define Nc 1024
#define Mc 2048
#define Dc 1024

// fp16 scratch (allocation-free rule)
__device__ __half g_textH [(size_t)Bc * Nc * Dc];   // [b][n][d]
__device__ __half g_audioH[(size_t)Bc * Mc * Dc];   // [b][m][d]
__device__ __half g_attnH [(size_t)Bc * Nc * Mc];   // [b][n][m]

__device__ __forceinline__ void cp_async16(uint32_t dst, const void* src) {
    asm volatile("cp.async.cg.shared.global [%0], [%1], 16;" :: "r"(dst), "l"(src) : "memory");
}
__device__ __forceinline__ void mma_f16(float* c, const uint32_t* a, const uint32_t* b) {
    asm volatile(
        "mma.sync.aligned.m16n8k16.row.col.f32.f16.f16.f32 "
        "{%0,%1,%2,%3}, {%4,%5,%6,%7}, {%8,%9}, {%0,%1,%2,%3};"
        : "+f"(c[0]), "+f"(c[1]), "+f"(c[2]), "+f"(c[3])
        : "r"(a[0]), "r"(a[1]), "r"(a[2]), "r"(a[3]), "r"(b[0]), "r"(b[1]));
}
__device__ __forceinline__ void ldsm_x4(uint32_t* r, uint32_t addr) {
    asm volatile("ldmatrix.sync.aligned.m8n8.x4.shared.b16 {%0,%1,%2,%3}, [%4];"
        : "=r"(r[0]), "=r"(r[1]), "=r"(r[2]), "=r"(r[3]) : "r"(addr));
}
__device__ __forceinline__ void ldsm_x4_t(uint32_t* r, uint32_t addr) {
    asm volatile("ldmatrix.sync.aligned.m8n8.x4.trans.shared.b16 {%0,%1,%2,%3}, [%4];"
        : "=r"(r[0]), "=r"(r[1]), "=r"(r[2]), "=r"(r[3]) : "r"(addr));
}

#define BM 128         // CTA rows (out rows)
#define BN 64          // CTA cols (out cols)
#define BK 32          // K chunk per stage (halfs)
#define AS 40          // A (and GEMM1-B) smem row stride in halfs
#define BS 72          // trans-B smem row stride in halfs (144 B: CF for LDSM)
#define A_HB (BM * AS * 2)              // 10240 B

// ---------------------------------------------------------------------------
// fp16 tensor-core GEMM: D[128x64] = A[128xK] . op(B) per CTA tile.
// 4 warps (32x64 warp tile), m16n8k16, ldmatrix, 3-stage cp.async pipeline.
//  BIAS  : GEMM1 — fuse /sqrt(D)+Gaussian bias; early-exit m-tiles >= len.
//  KDYN  : GEMM2 — runtime K bound = round_up(len, BK).
//  BTRANS: B global is [k][n] row-major (audioH for GEMM2); load with
//          ldmatrix.trans. Else B is [n][k] K-major.
// ---------------------------------------------------------------------------
template<int KTOT, bool BIAS, bool KDYN, bool BTRANS>
__global__ __launch_bounds__(128, 4) void tc_gemm(
    const __half* __restrict__ Ag, const __half* __restrict__ Bg,
    float* __restrict__ Og,
    size_t sA, size_t sB, size_t sO,
    int ldA, int ldB, int ldO,
    const float* __restrict__ sigma,
    const int* __restrict__ lens)
{
    constexpr uint32_t B_HB    = BTRANS ? (BK * BS * 2) : (BN * AS * 2);
    constexpr uint32_t STAGE_B = A_HB + B_HB;
    constexpr int NSTAGE = 3;

    const int b  = blockIdx.z;
    const int r0 = blockIdx.y * BM;
    const int c0 = blockIdx.x * BN;

    const int len = lens[b];
    if (BIAS && c0 >= len) return;   // masked m-tile: softmax writes 0 anyway

    constexpr int NSTC = KTOT / BK;
    const int nst = KDYN ? ((len + BK - 1) >> 5) : NSTC;   // >= 16 (len >= 512)

    extern __shared__ char smc[];
    const uint32_t smemU = (uint32_t)__cvta_generic_to_shared(smc);
    const int tid  = threadIdx.x;
    const int lane = tid & 31;
    const int wid  = tid >> 5;          // 0..3
    const int wm0  = wid * 32;          // warp row offset
    const int gq   = lane >> 2;
    const int tg   = lane & 3;

    const __half* Ab = Ag + (size_t)b * sA + (size_t)r0 * ldA;
    // BTRANS: col offset; else row offset
    const __half* Bb = Bg + (size_t)b * sB + (BTRANS ? (size_t)c0 : (size_t)c0 * ldB);

    // ldmatrix per-lane base byte offsets within a stage
    const uint32_t aOff = (uint32_t)(((wm0 + (lane & 15)) * AS + (lane >> 4) * 8) * 2);
    // GEMM1 B (non-trans): rows are n, tiles [n0-7,k0-7][n0-7,k8-15][n8-15,..]
    const uint32_t bOffN = A_HB +
        (uint32_t)(((((lane >> 4) << 3) + (lane & 7)) * AS + ((lane >> 3) & 1) * 8) * 2);
    // GEMM2 B (trans): rows are k; tile p=lane>>3: k-half=p&1, n-half=p>>1
    const uint32_t bOffT = A_HB +
        (uint32_t)(((((lane >> 3) & 1) * 8 + (lane & 7)) * BS + ((lane >> 4) * 8)) * 2);

    float acc[2][8][4];
    #pragma unroll
    for (int mt = 0; mt < 2; ++mt)
        #pragma unroll
        for (int nt = 0; nt < 8; ++nt)
            #pragma unroll
            for (int r = 0; r < 4; ++r) acc[mt][nt][r] = 0.0f;

    auto issue = [&](int c) {
        const int s  = c % NSTAGE;
        const int k0 = c * BK;
        #pragma unroll
        for (int i = 0; i < 6; ++i) {
            const int q   = tid + i * 128;     // 0..767
            const int isB = q >> 9;            // >=512 -> B
            const int qq  = isB ? (q - 512) : q;
            const char* src;
            uint32_t off;
            if (!isB) {
                const int row = qq >> 2, seg = qq & 3;
                src = (const char*)(Ab + (size_t)row * ldA + k0) + seg * 16;
                off = (uint32_t)(row * (AS * 2) + seg * 16);
            } else if (!BTRANS) {
                const int row = qq >> 2, seg = qq & 3;
                src = (const char*)(Bb + (size_t)row * ldB + k0) + seg * 16;
                off = A_HB + (uint32_t)(row * (AS * 2) + seg * 16);
            } else {
                const int kr = qq >> 3, seg = qq & 7;   // 32 k-rows x 8 segs
                src = (const char*)(Bb + (size_t)(k0 + kr) * ldB) + seg * 16;
                off = A_HB + (uint32_t)(kr * (BS * 2) + seg * 16);
            }
            cp_async16(smemU + s * STAGE_B + off, src);
        }
        asm volatile("cp.async.commit_group;" ::: "memory");
    };

    issue(0);
    issue(1);
    for (int c = 0; c < nst; ++c) {
        if (c + 1 < nst) asm volatile("cp.async.wait_group 1;" ::: "memory");
        else             asm volatile("cp.async.wait_group 0;" ::: "memory");
        __syncthreads();
        if (c + 2 < nst) issue(c + 2);

        const uint32_t stg = smemU + (c % NSTAGE) * STAGE_B;

        #pragma unroll
        for (int ks = 0; ks < 2; ++ks) {
            uint32_t af[2][4], bf[8][2];
            #pragma unroll
            for (int mt = 0; mt < 2; ++mt)
                ldsm_x4(af[mt], stg + aOff + mt * (16 * AS * 2) + ks * 32);
            #pragma unroll
            for (int p = 0; p < 4; ++p) {
                uint32_t r[4];
                if (!BTRANS) {
                    ldsm_x4(r, stg + bOffN + p * (16 * AS * 2) + ks * 32);
                } else {
                    // ks selects 16 k-rows; p selects 16 n-cols
                    ldsm_x4_t(r, stg + bOffT + ks * (16 * BS * 2) + p * 32);
                }
                bf[2 * p][0] = r[0];     bf[2 * p][1] = r[1];
                bf[2 * p + 1][0] = r[2]; bf[2 * p + 1][1] = r[3];
            }
            #pragma unroll
            for (int mt = 0; mt < 2; ++mt)
                #pragma unroll
                for (int nt = 0; nt < 8; ++nt)
                    mma_f16(acc[mt][nt], af[mt], bf[nt]);
        }
    }

    // ------------------------------------------------------------------ epi
    float inv2s2 = 0.f;
    if (BIAS) {
        const float s = fabsf(sigma[0]) + 1e-8f;
        inv2s2 = 1.0f / (2.0f * s * s);
    }

    #pragma unroll
    for (int mt = 0; mt < 2; ++mt) {
        #pragma unroll
        for (int h = 0; h < 2; ++h) {
            const int rn = r0 + wm0 + mt * 16 + gq + h * 8;
            float* orow = Og + (size_t)b * sO + (size_t)rn * ldO;
            const float npos = (float)rn * (1.0f / Nc);
            #pragma unroll
            for (int nt = 0; nt < 8; ++nt) {
                const int cn = c0 + nt * 8 + 2 * tg;
                float2 v = make_float2(acc[mt][nt][h * 2 + 0],
                                       acc[mt][nt][h * 2 + 1]);
                if (BIAS) {
                    const float d0 = npos - (float)(cn + 0) * (1.0f / Mc);
                    const float d1 = npos - (float)(cn + 1) * (1.0f / Mc);
                    v.x = v.x * 0.03125f - d0 * d0 * inv2s2;
                    v.y = v.y * 0.03125f - d1 * d1 * inv2s2;
                }
                *(float2*)(orow + cn) = v;
            }
        }
    }
}

#define SMEM_G1 (3 * (A_HB + BN * AS * 2))   // 46080 B
#define SMEM_G2 (3 * (A_HB + BK * BS * 2))   // 44544 B

// ---------------------------------------------------------------------------
// fp32 -> fp16 streaming convert (8 elements/thread)
// ---------------------------------------------------------------------------
__global__ __launch_bounds__(256) void cvt_h(
    const float* __restrict__ in, __half* __restrict__ out)
{
    const size_t i = ((size_t)blockIdx.x * 256 + threadIdx.x) * 8;
    float4 a = *(const float4*)(in + i);
    float4 b = *(const float4*)(in + i + 4);
    __half2 h[4] = {
        __floats2half2_rn(a.x, a.y), __floats2half2_rn(a.z, a.w),
        __floats2half2_rn(b.x, b.y), __floats2half2_rn(b.z, b.w) };
    *(uint4*)(out + i) = *(const uint4*)h;
}

// ---------------------------------------------------------------------------
// Masked row softmax over M=2048; one block of 256 per (b,n) row.
// Skips loads for fully-masked 8-groups; writes fp32 full row (zeros past
// len) + fp16 copy up to round_up(len,32) (all GEMM2 reads).
// ---------------------------------------------------------------------------
__global__ __launch_bounds__(256) void softmax_rows(
    float* __restrict__ attn, const int* __restrict__ lens)
{
    const int row = blockIdx.x;
    const int b = row >> 10;
    const int len = lens[b];
    const int lenR = (len + 31) & ~31;
    float*  P  = attn    + (size_t)row * Mc;
    __half* PH = g_attnH + (size_t)row * Mc;
    const int tid  = threadIdx.x;
    const int lane = tid & 31;
    const int wrp  = tid >> 5;
    const int j0   = tid * 8;

    __shared__ float red[8];

    float vals[8];
    if (j0 < len) {
        float4 v0 = *(const float4*)(P + j0);
        float4 v1 = *(const float4*)(P + j0 + 4);
        vals[0] = (j0 + 0 < len) ? v0.x : -INFINITY;
        vals[1] = (j0 + 1 < len) ? v0.y : -INFINITY;
        vals[2] = (j0 + 2 < len) ? v0.z : -INFINITY;
        vals[3] = (j0 + 3 < len) ? v0.w : -INFINITY;
        vals[4] = (j0 + 4 < len) ? v1.x : -INFINITY;
        vals[5] = (j0 + 5 < len) ? v1.y : -INFINITY;
        vals[6] = (j0 + 6 < len) ? v1.z : -INFINITY;
        vals[7] = (j0 + 7 < len) ? v1.w : -INFINITY;
    } else {
        #pragma unroll
        for (int t = 0; t < 8; ++t) vals[t] = -INFINITY;
    }

    float mx = vals[0];
    #pragma unroll
    for (int t = 1; t < 8; ++t) mx = fmaxf(mx, vals[t]);
    #pragma unroll
    for (int o = 16; o > 0; o >>= 1) mx = fmaxf(mx, __shfl_xor_sync(~0u, mx, o));
    if (lane == 0) red[wrp] = mx;
    __syncthreads();
    {
        float t = red[lane & 7];
        #pragma unroll
        for (int o = 4; o > 0; o >>= 1) t = fmaxf(t, __shfl_xor_sync(~0u, t, o));
        mx = t;
    }

    float sum = 0.0f;
    #pragma unroll
    for (int t = 0; t < 8; ++t) {
        const float e = (vals[t] == -INFINITY) ? 0.0f : __expf(vals[t] - mx);
        vals[t] = e;
        sum += e;
    }
    #pragma unroll
    for (int o = 16; o > 0; o >>= 1) sum += __shfl_xor_sync(~0u, sum, o);
    __syncthreads();
    if (lane == 0) red[wrp] = sum;
    __syncthreads();
    {
        float t = red[lane & 7];
        #pragma unroll
        for (int o = 4; o > 0; o >>= 1) t += __shfl_xor_sync(~0u, t, o);
        sum = t;
    }
    const float inv = 1.0f / sum;

    float w[8];
    #pragma unroll
    for (int t = 0; t < 8; ++t) w[t] = vals[t] * inv;

    *(float4*)(P + j0)     = make_float4(w[0], w[1], w[2], w[3]);
    *(float4*)(P + j0 + 4) = make_float4(w[4], w[5], w[6], w[7]);

    if (j0 < lenR) {
        __half2 h[4] = {
            __floats2half2_rn(w[0], w[1]), __floats2half2_rn(w[2], w[3]),
            __floats2half2_rn(w[4], w[5]), __floats2half2_rn(w[6], w[7]) };
        *(uint4*)(PH + j0) = *(const uint4*)h;
    }
}

// ---------------------------------------------------------------------------
extern "C" void kernel_launch(void* const* d_in, const int* in_sizes, int n_in,
                              void* d_out, int out_size)
{
    const float* text  = (const float*)d_in[0];
    const float* audio = (const float*)d_in[1];
    const float* sigma = (const float*)d_in[2];
    const int*   lens  = (const int*)d_in[3];

    float* enhanced = (float*)d_out;                    // B*N*D
    float* attn     = enhanced + (size_t)Bc * Nc * Dc;  // B*N*M (scores scratch)

    void *textH_p = nullptr, *audioH_p = nullptr, *attnH_p = nullptr;
    cudaGetSymbolAddress(&textH_p,  g_textH);
    cudaGetSymbolAddress(&audioH_p, g_audioH);
    cudaGetSymbolAddress(&attnH_p,  g_attnH);

    cudaFuncSetAttribute(tc_gemm<Dc, true, false, false>,
                         cudaFuncAttributeMaxDynamicSharedMemorySize, SMEM_G1);
    cudaFuncSetAttribute(tc_gemm<Mc, false, true, true>,
                         cudaFuncAttributeMaxDynamicSharedMemorySize, SMEM_G2);

    cvt_h<<<(Bc * Nc * Dc) / 2048, 256>>>(text,  (__half*)textH_p);
    cvt_h<<<(Bc * Mc * Dc) / 2048, 256>>>(audio, (__half*)audioH_p);

    // GEMM1: scores = textH . audioH^T (+bias) -> attn; skips m-tiles >= len
    tc_gemm<Dc, true, false, false><<<dim3(Mc / BN, Nc / BM, Bc), 128, SMEM_G1>>>(
        (const __half*)textH_p, (const __half*)audioH_p, attn,
        (size_t)Nc * Dc, (size_t)Mc * Dc, (size_t)Nc * Mc,
        Dc, Dc, Mc, sigma, lens);

    softmax_rows<<<Bc * Nc, 256>>>(attn, lens);

    // GEMM2: enhanced = attnH . audioH (trans-B); K bounded by round_up(len,32)
    tc_gemm<Mc, false, true, true><<<dim3(Dc / BN, Nc / BM, Bc), 128, SMEM_G2>>>(
        (const __half*)attnH_p, (const __half*)audioH_p, enhanced,
        (size_t)Nc * Mc, (size_t)Mc * Dc, (size_t)Nc * Dc,
        Mc, Dc, Dc, nullptr, lens);
}

// round 17
// speedup vs baseline: 2.7804x; 1.0031x over previous
#include <cuda_runtime.h>
#include <cuda_fp16.h>
#include <math.h>
#include <stdint.h>

#define Bc 8
#define Nc 1024
#define Mc 2048
#define Dc 1024

// fp16 scratch (allocation-free rule)
__device__ __half g_textH [(size_t)Bc * Nc * Dc];   // [b][n][d]
__device__ __half g_audioH[(size_t)Bc * Mc * Dc];   // [b][m][d]
__device__ __half g_attnH [(size_t)Bc * Nc * Mc];   // [b][n][m]

__device__ __forceinline__ void cp_async16(uint32_t dst, const void* src) {
    asm volatile("cp.async.cg.shared.global [%0], [%1], 16;" :: "r"(dst), "l"(src) : "memory");
}
__device__ __forceinline__ void mma_f16(float* c, const uint32_t* a, const uint32_t* b) {
    asm volatile(
        "mma.sync.aligned.m16n8k16.row.col.f32.f16.f16.f32 "
        "{%0,%1,%2,%3}, {%4,%5,%6,%7}, {%8,%9}, {%0,%1,%2,%3};"
        : "+f"(c[0]), "+f"(c[1]), "+f"(c[2]), "+f"(c[3])
        : "r"(a[0]), "r"(a[1]), "r"(a[2]), "r"(a[3]), "r"(b[0]), "r"(b[1]));
}
__device__ __forceinline__ void ldsm_x4(uint32_t* r, uint32_t addr) {
    asm volatile("ldmatrix.sync.aligned.m8n8.x4.shared.b16 {%0,%1,%2,%3}, [%4];"
        : "=r"(r[0]), "=r"(r[1]), "=r"(r[2]), "=r"(r[3]) : "r"(addr));
}
__device__ __forceinline__ void ldsm_x4_t(uint32_t* r, uint32_t addr) {
    asm volatile("ldmatrix.sync.aligned.m8n8.x4.trans.shared.b16 {%0,%1,%2,%3}, [%4];"
        : "=r"(r[0]), "=r"(r[1]), "=r"(r[2]), "=r"(r[3]) : "r"(addr));
}

#define BM 128         // CTA rows (out rows)
#define BN 64          // CTA cols (out cols)
#define BK 32          // K chunk per stage (halfs)
#define AS 40          // A (and GEMM1-B) smem row stride in halfs
#define BS 72          // trans-B smem row stride in halfs (144 B: CF for LDSM)
#define A_HB (BM * AS * 2)              // 10240 B

// ---------------------------------------------------------------------------
// fp16 tensor-core GEMM: D[128x64] = A[128xK] . op(B) per CTA tile.
// 4 warps (32x64 warp tile), m16n8k16, ldmatrix, 3-stage cp.async pipeline.
//  BIAS  : GEMM1 — fuse /sqrt(D)+Gaussian bias; masked m-tiles (c0>=len)
//          write their fp32 zero tile and return (off-critical-path fill).
//  KDYN  : GEMM2 — runtime K bound = round_up(len, BK).
//  BTRANS: B global is [k][n] row-major (audioH for GEMM2); ldmatrix.trans.
// ---------------------------------------------------------------------------
template<int KTOT, bool BIAS, bool KDYN, bool BTRANS>
__global__ __launch_bounds__(128, 4) void tc_gemm(
    const __half* __restrict__ Ag, const __half* __restrict__ Bg,
    float* __restrict__ Og,
    size_t sA, size_t sB, size_t sO,
    int ldA, int ldB, int ldO,
    const float* __restrict__ sigma,
    const int* __restrict__ lens)
{
    constexpr uint32_t B_HB    = BTRANS ? (BK * BS * 2) : (BN * AS * 2);
    constexpr uint32_t STAGE_B = A_HB + B_HB;
    constexpr int NSTAGE = 3;

    const int b  = blockIdx.z;
    const int r0 = blockIdx.y * BM;
    const int c0 = blockIdx.x * BN;

    const int len = lens[b];
    const int tid = threadIdx.x;

    if (BIAS && c0 >= len) {
        // Fully-masked m-tile: fill our 128x64 fp32 output tile with zeros
        // (softmax will not write fp32 past round_up(len,64)).
        float* base = Og + (size_t)b * sO + (size_t)r0 * ldO + c0;
        const float4 z = make_float4(0.f, 0.f, 0.f, 0.f);
        #pragma unroll
        for (int i = 0; i < 16; ++i) {
            const int q   = tid + i * 128;     // 0..2047
            const int row = q >> 4;
            const int seg = q & 15;
            *(float4*)(base + (size_t)row * ldO + seg * 4) = z;
        }
        return;
    }

    constexpr int NSTC = KTOT / BK;
    const int nst = KDYN ? ((len + BK - 1) >> 5) : NSTC;   // >= 16 (len >= 512)

    extern __shared__ char smc[];
    const uint32_t smemU = (uint32_t)__cvta_generic_to_shared(smc);
    const int lane = tid & 31;
    const int wid  = tid >> 5;          // 0..3
    const int wm0  = wid * 32;          // warp row offset
    const int gq   = lane >> 2;
    const int tg   = lane & 3;

    const __half* Ab = Ag + (size_t)b * sA + (size_t)r0 * ldA;
    const __half* Bb = Bg + (size_t)b * sB + (BTRANS ? (size_t)c0 : (size_t)c0 * ldB);

    // ldmatrix per-lane base byte offsets within a stage
    const uint32_t aOff = (uint32_t)(((wm0 + (lane & 15)) * AS + (lane >> 4) * 8) * 2);
    const uint32_t bOffN = A_HB +
        (uint32_t)(((((lane >> 4) << 3) + (lane & 7)) * AS + ((lane >> 3) & 1) * 8) * 2);
    const uint32_t bOffT = A_HB +
        (uint32_t)(((((lane >> 3) & 1) * 8 + (lane & 7)) * BS + ((lane >> 4) * 8)) * 2);

    float acc[2][8][4];
    #pragma unroll
    for (int mt = 0; mt < 2; ++mt)
        #pragma unroll
        for (int nt = 0; nt < 8; ++nt)
            #pragma unroll
            for (int r = 0; r < 4; ++r) acc[mt][nt][r] = 0.0f;

    auto issue = [&](int c) {
        const int s  = c % NSTAGE;
        const int k0 = c * BK;
        #pragma unroll
        for (int i = 0; i < 6; ++i) {
            const int q   = tid + i * 128;     // 0..767
            const int isB = q >> 9;            // >=512 -> B
            const int qq  = isB ? (q - 512) : q;
            const char* src;
            uint32_t off;
            if (!isB) {
                const int row = qq >> 2, seg = qq & 3;
                src = (const char*)(Ab + (size_t)row * ldA + k0) + seg * 16;
                off = (uint32_t)(row * (AS * 2) + seg * 16);
            } else if (!BTRANS) {
                const int row = qq >> 2, seg = qq & 3;
                src = (const char*)(Bb + (size_t)row * ldB + k0) + seg * 16;
                off = A_HB + (uint32_t)(row * (AS * 2) + seg * 16);
            } else {
                const int kr = qq >> 3, seg = qq & 7;   // 32 k-rows x 8 segs
                src = (const char*)(Bb + (size_t)(k0 + kr) * ldB) + seg * 16;
                off = A_HB + (uint32_t)(kr * (BS * 2) + seg * 16);
            }
            cp_async16(smemU + s * STAGE_B + off, src);
        }
        asm volatile("cp.async.commit_group;" ::: "memory");
    };

    issue(0);
    issue(1);
    for (int c = 0; c < nst; ++c) {
        if (c + 1 < nst) asm volatile("cp.async.wait_group 1;" ::: "memory");
        else             asm volatile("cp.async.wait_group 0;" ::: "memory");
        __syncthreads();
        if (c + 2 < nst) issue(c + 2);

        const uint32_t stg = smemU + (c % NSTAGE) * STAGE_B;

        #pragma unroll
        for (int ks = 0; ks < 2; ++ks) {
            uint32_t af[2][4], bf[8][2];
            #pragma unroll
            for (int mt = 0; mt < 2; ++mt)
                ldsm_x4(af[mt], stg + aOff + mt * (16 * AS * 2) + ks * 32);
            #pragma unroll
            for (int p = 0; p < 4; ++p) {
                uint32_t r[4];
                if (!BTRANS) {
                    ldsm_x4(r, stg + bOffN + p * (16 * AS * 2) + ks * 32);
                } else {
                    ldsm_x4_t(r, stg + bOffT + ks * (16 * BS * 2) + p * 32);
                }
                bf[2 * p][0] = r[0];     bf[2 * p][1] = r[1];
                bf[2 * p + 1][0] = r[2]; bf[2 * p + 1][1] = r[3];
            }
            #pragma unroll
            for (int mt = 0; mt < 2; ++mt)
                #pragma unroll
                for (int nt = 0; nt < 8; ++nt)
                    mma_f16(acc[mt][nt], af[mt], bf[nt]);
        }
    }

    // ------------------------------------------------------------------ epi
    float inv2s2 = 0.f;
    if (BIAS) {
        const float s = fabsf(sigma[0]) + 1e-8f;
        inv2s2 = 1.0f / (2.0f * s * s);
    }

    #pragma unroll
    for (int mt = 0; mt < 2; ++mt) {
        #pragma unroll
        for (int h = 0; h < 2; ++h) {
            const int rn = r0 + wm0 + mt * 16 + gq + h * 8;
            float* orow = Og + (size_t)b * sO + (size_t)rn * ldO;
            const float npos = (float)rn * (1.0f / Nc);
            #pragma unroll
            for (int nt = 0; nt < 8; ++nt) {
                const int cn = c0 + nt * 8 + 2 * tg;
                float2 v = make_float2(acc[mt][nt][h * 2 + 0],
                                       acc[mt][nt][h * 2 + 1]);
                if (BIAS) {
                    const float d0 = npos - (float)(cn + 0) * (1.0f / Mc);
                    const float d1 = npos - (float)(cn + 1) * (1.0f / Mc);
                    v.x = v.x * 0.03125f - d0 * d0 * inv2s2;
                    v.y = v.y * 0.03125f - d1 * d1 * inv2s2;
                }
                *(float2*)(orow + cn) = v;
            }
        }
    }
}

#define SMEM_G1 (3 * (A_HB + BN * AS * 2))   // 46080 B
#define SMEM_G2 (3 * (A_HB + BK * BS * 2))   // 44544 B

// ---------------------------------------------------------------------------
// fp32 -> fp16 streaming convert (8 elements/thread)
// ---------------------------------------------------------------------------
__global__ __launch_bounds__(256) void cvt_h(
    const float* __restrict__ in, __half* __restrict__ out)
{
    const size_t i = ((size_t)blockIdx.x * 256 + threadIdx.x) * 8;
    float4 a = *(const float4*)(in + i);
    float4 b = *(const float4*)(in + i + 4);
    __half2 h[4] = {
        __floats2half2_rn(a.x, a.y), __floats2half2_rn(a.z, a.w),
        __floats2half2_rn(b.x, b.y), __floats2half2_rn(b.z, b.w) };
    *(uint4*)(out + i) = *(const uint4*)h;
}

// ---------------------------------------------------------------------------
// Masked row softmax over M=2048; one block of 256 per (b,n) row.
// Loads: fast path for fully-unmasked 8-groups; no loads past len.
// Stores: fp32 for j0 < round_up(len,64) (GEMM1 skip-CTAs zero the rest);
//         fp16 for j0 < round_up(len,32) (all GEMM2 reads).
// ---------------------------------------------------------------------------
__global__ __launch_bounds__(256) void softmax_rows(
    float* __restrict__ attn, const int* __restrict__ lens)
{
    const int row = blockIdx.x;
    const int b = row >> 10;
    const int len  = lens[b];
    const int lenR = (len + 31) & ~31;
    const int lenT = (len + 63) & ~63;
    float*  P  = attn    + (size_t)row * Mc;
    __half* PH = g_attnH + (size_t)row * Mc;
    const int tid  = threadIdx.x;
    const int lane = tid & 31;
    const int wrp  = tid >> 5;
    const int j0   = tid * 8;

    __shared__ float red[8];

    float vals[8];
    if (j0 + 8 <= len) {                       // fully unmasked (common)
        float4 v0 = *(const float4*)(P + j0);
        float4 v1 = *(const float4*)(P + j0 + 4);
        vals[0] = v0.x; vals[1] = v0.y; vals[2] = v0.z; vals[3] = v0.w;
        vals[4] = v1.x; vals[5] = v1.y; vals[6] = v1.z; vals[7] = v1.w;
    } else if (j0 < len) {                     // edge group
        float4 v0 = *(const float4*)(P + j0);
        float4 v1 = *(const float4*)(P + j0 + 4);
        vals[0] = (j0 + 0 < len) ? v0.x : -INFINITY;
        vals[1] = (j0 + 1 < len) ? v0.y : -INFINITY;
        vals[2] = (j0 + 2 < len) ? v0.z : -INFINITY;
        vals[3] = (j0 + 3 < len) ? v0.w : -INFINITY;
        vals[4] = (j0 + 4 < len) ? v1.x : -INFINITY;
        vals[5] = (j0 + 5 < len) ? v1.y : -INFINITY;
        vals[6] = (j0 + 6 < len) ? v1.z : -INFINITY;
        vals[7] = (j0 + 7 < len) ? v1.w : -INFINITY;
    } else {                                   // fully masked
        #pragma unroll
        for (int t = 0; t < 8; ++t) vals[t] = -INFINITY;
    }

    float mx = vals[0];
    #pragma unroll
    for (int t = 1; t < 8; ++t) mx = fmaxf(mx, vals[t]);
    #pragma unroll
    for (int o = 16; o > 0; o >>= 1) mx = fmaxf(mx, __shfl_xor_sync(~0u, mx, o));
    if (lane == 0) red[wrp] = mx;
    __syncthreads();
    {
        float t = red[lane & 7];
        #pragma unroll
        for (int o = 4; o > 0; o >>= 1) t = fmaxf(t, __shfl_xor_sync(~0u, t, o));
        mx = t;
    }

    float sum = 0.0f;
    #pragma unroll
    for (int t = 0; t < 8; ++t) {
        const float e = (vals[t] == -INFINITY) ? 0.0f : __expf(vals[t] - mx);
        vals[t] = e;
        sum += e;
    }
    #pragma unroll
    for (int o = 16; o > 0; o >>= 1) sum += __shfl_xor_sync(~0u, sum, o);
    __syncthreads();
    if (lane == 0) red[wrp] = sum;
    __syncthreads();
    {
        float t = red[lane & 7];
        #pragma unroll
        for (int o = 4; o > 0; o >>= 1) t += __shfl_xor_sync(~0u, t, o);
        sum = t;
    }
    const float inv = 1.0f / sum;

    float w[8];
    #pragma unroll
    for (int t = 0; t < 8; ++t) w[t] = vals[t] * inv;

    if (j0 < lenT) {   // GEMM1 skip-CTAs zeroed j0 >= lenT already
        *(float4*)(P + j0)     = make_float4(w[0], w[1], w[2], w[3]);
        *(float4*)(P + j0 + 4) = make_float4(w[4], w[5], w[6], w[7]);
    }
    if (j0 < lenR) {
        __half2 h[4] = {
            __floats2half2_rn(w[0], w[1]), __floats2half2_rn(w[2], w[3]),
            __floats2half2_rn(w[4], w[5]), __floats2half2_rn(w[6], w[7]) };
        *(uint4*)(PH + j0) = *(const uint4*)h;
    }
}

// ---------------------------------------------------------------------------
extern "C" void kernel_launch(void* const* d_in, const int* in_sizes, int n_in,
                              void* d_out, int out_size)
{
    const float* text  = (const float*)d_in[0];
    const float* audio = (const float*)d_in[1];
    const float* sigma = (const float*)d_in[2];
    const int*   lens  = (const int*)d_in[3];

    float* enhanced = (float*)d_out;                    // B*N*D
    float* attn     = enhanced + (size_t)Bc * Nc * Dc;  // B*N*M (scores scratch)

    void *textH_p = nullptr, *audioH_p = nullptr, *attnH_p = nullptr;
    cudaGetSymbolAddress(&textH_p,  g_textH);
    cudaGetSymbolAddress(&audioH_p, g_audioH);
    cudaGetSymbolAddress(&attnH_p,  g_attnH);

    cudaFuncSetAttribute(tc_gemm<Dc, true, false, false>,
                         cudaFuncAttributeMaxDynamicSharedMemorySize, SMEM_G1);
    cudaFuncSetAttribute(tc_gemm<Mc, false, true, true>,
                         cudaFuncAttributeMaxDynamicSharedMemorySize, SMEM_G2);

    cvt_h<<<(Bc * Nc * Dc) / 2048, 256>>>(text,  (__half*)textH_p);
    cvt_h<<<(Bc * Mc * Dc) / 2048, 256>>>(audio, (__half*)audioH_p);

    // GEMM1: scores = textH . audioH^T (+bias) -> attn;
    // masked m-tiles write zeros instead of computing.
    tc_gemm<Dc, true, false, false><<<dim3(Mc / BN, Nc / BM, Bc), 128, SMEM_G1>>>(
        (const __half*)textH_p, (const __half*)audioH_p, attn,
        (size_t)Nc * Dc, (size_t)Mc * Dc, (size_t)Nc * Mc,
        Dc, Dc, Mc, sigma, lens);

    softmax_rows<<<Bc * Nc, 256>>>(attn, lens);

    // GEMM2: enhanced = attnH . audioH (trans-B); K bounded by round_up(len,32)
    tc_gemm<Mc, false, true, true><<<dim3(Dc / BN, Nc / BM, Bc), 128, SMEM_G2>>>(
        (const __half*)attnH_p, (const __half*)audioH_p, enhanced,
        (size_t)Nc * Mc, (size_t)Mc * Dc, (size_t)Nc * Dc,
        Mc, Dc, Dc, nullptr, lens);
}